// round 3
// baseline (speedup 1.0000x reference)
#include <cuda_runtime.h>
#include <math.h>
#include <stdint.h>

// ---------------- problem constants ----------------
constexpr int kNL = 4;
constexpr int kD  = 1024;
constexpr int kD2 = 2048;
constexpr int kH  = 16;
constexpr int kDH = 64;
constexpr int kV  = 32000;
constexpr int kB  = 2;
constexpr int kL  = 2048;
constexpr int kBL = kB * kL;   // 4096
#define EPSF 1e-6f

// ---------------- scratch (device globals; no allocation allowed) ----------------
__device__ float g_x[kBL * kD];
__device__ float g_h[kBL * kD];
__device__ float g_q[kBL * kD];
__device__ float g_k[kBL * kD];
__device__ float g_v[kBL * kD];
__device__ float g_att[kBL * kD];
__device__ float g_proj[(size_t)kBL * kD2];
__device__ float g_up[(size_t)kBL * kD2];

// ---------------- small helpers ----------------
__device__ __forceinline__ uint32_t f2tf32(float f) {
    uint32_t u;
    asm("cvt.rna.tf32.f32 %0, %1;" : "=r"(u) : "f"(f));
    return u;
}
__device__ __forceinline__ void mma_tf32(float* c, const uint32_t* a, uint32_t b0, uint32_t b1) {
    asm volatile(
        "mma.sync.aligned.m16n8k8.row.col.f32.tf32.tf32.f32 "
        "{%0,%1,%2,%3}, {%4,%5,%6,%7}, {%8,%9}, {%0,%1,%2,%3};"
        : "+f"(c[0]), "+f"(c[1]), "+f"(c[2]), "+f"(c[3])
        : "r"(a[0]), "r"(a[1]), "r"(a[2]), "r"(a[3]), "r"(b0), "r"(b1));
}
__device__ __forceinline__ void cp16(uint32_t dst, const float* src) {
    asm volatile("cp.async.cg.shared.global [%0], [%1], 16;" :: "r"(dst), "l"(src));
}

// ---------------- embed + positional encoding ----------------
__global__ void embed_pe_kernel(const int* __restrict__ ids,
                                const float* __restrict__ embed,
                                float* __restrict__ x)
{
    int row = blockIdx.x;
    int l   = row % kL;
    int id  = ids[row];
    int d0  = threadIdx.x * 4;
    float4 ev = *(const float4*)&embed[(size_t)id * kD + d0];
    float out[4] = {ev.x, ev.y, ev.z, ev.w};
    const float negc = -0.0089944731f;   // -log(10000)/1024 in fp32
#pragma unroll
    for (int t = 0; t < 4; ++t) {
        int d  = d0 + t;
        int i2 = (d >> 1) * 2;
        float freq = expf((float)i2 * negc);
        float a    = (float)l * freq;
        out[t] += (d & 1) ? cosf(a) : sinf(a);
    }
    *(float4*)&x[(size_t)row * kD + d0] = make_float4(out[0], out[1], out[2], out[3]);
}

// ---------------- rmsnorm ----------------
__global__ void rmsnorm_kernel(const float* __restrict__ x,
                               const float* __restrict__ gamma,
                               float* __restrict__ y)
{
    int row = blockIdx.x;
    const float* xr = x + (size_t)row * kD;
    int d0 = threadIdx.x * 4;
    float4 v = *(const float4*)&xr[d0];
    float ss = v.x * v.x + v.y * v.y + v.z * v.z + v.w * v.w;
#pragma unroll
    for (int off = 16; off; off >>= 1)
        ss += __shfl_xor_sync(0xffffffffu, ss, off);
    __shared__ float ws[8];
    int lane = threadIdx.x & 31, w = threadIdx.x >> 5;
    if (lane == 0) ws[w] = ss;
    __syncthreads();
    if (w == 0) {
        float t = (lane < 8) ? ws[lane] : 0.0f;
#pragma unroll
        for (int off = 4; off; off >>= 1)
            t += __shfl_xor_sync(0xffffffffu, t, off);
        if (lane == 0) ws[0] = t;
    }
    __syncthreads();
    float scale = rsqrtf(ws[0] / (float)kD + EPSF);
    float4 g = *(const float4*)&gamma[d0];
    float4 o = make_float4(v.x * scale * g.x, v.y * scale * g.y,
                           v.z * scale * g.z, v.w * scale * g.w);
    *(float4*)&y[(size_t)row * kD + d0] = o;
}

// ---------------- silu gate: proj = silu(proj * up) ----------------
__global__ void silu_gate_kernel(float* __restrict__ proj,
                                 const float* __restrict__ up)
{
    size_t i = ((size_t)blockIdx.x * blockDim.x + threadIdx.x) * 4;
    float4 p = *(float4*)&proj[i];
    float4 u = *(const float4*)&up[i];
    float t0 = p.x * u.x, t1 = p.y * u.y, t2 = p.z * u.z, t3 = p.w * u.w;
    p.x = t0 / (1.0f + __expf(-t0));
    p.y = t1 / (1.0f + __expf(-t1));
    p.z = t2 / (1.0f + __expf(-t2));
    p.w = t3 / (1.0f + __expf(-t3));
    *(float4*)&proj[i] = p;
}

// ================= TF32 tensor-core GEMM (pre-converted frag smem) =================
// 128x128x32 block tile, 8 warps (2x4), 64x32 warp tile, m16n8k8.tf32.
// cp.async -> raw staging; once-per-chunk convert pass writes tf32 bits into
// conflict-free frag layouts; inner loop is pure LDS+MMA (no cvt).

constexpr int kAP = 36;               // A frag pitch (floats)
constexpr int kBP = 132;              // B frag pitch
constexpr int kAF = 128 * kAP;        // 4608 u32
constexpr int kBF = 32 * kBP;         // 4224 u32
constexpr int kFrag = kAF + kBF;      // 8832 u32 per buffer
constexpr int kStgA = 128 * 32;       // 4096 floats
constexpr int kStgB = 32 * 128;       // 4096 floats
constexpr int kGemmSmem = (2 * kFrag + kStgA + kStgB) * 4;  // 103424 bytes

__global__ void __launch_bounds__(256, 2)
gemm_tf32_kernel(const float* __restrict__ A, const float* __restrict__ Bw,
                 const float* __restrict__ bias, const float* __restrict__ resid,
                 float* __restrict__ C, int M, int N, int K)
{
    extern __shared__ uint32_t smu[];
    uint32_t* frag = smu;                         // [2][kFrag]
    float* stgA = (float*)(smu + 2 * kFrag);      // [128][32]
    float* stgB = stgA + kStgA;                   // [32][128]
    uint32_t stgAaddr = (uint32_t)__cvta_generic_to_shared(stgA);
    uint32_t stgBaddr = (uint32_t)__cvta_generic_to_shared(stgB);

    int tid  = threadIdx.x;
    int lane = tid & 31;
    int warp = tid >> 5;
    int wm = warp >> 2;
    int wn = warp & 3;
    int bm = blockIdx.y, bn = blockIdx.x;

    const float* Ab = A + (size_t)bm * 128 * K;
    const float* Bb = Bw + (size_t)bn * 128;

    // per-thread load decomposition (4 float4 chunks each for A and B)
    int am[4], ak[4], bk[4], bn4[4];
    uint32_t adst[4], bdst[4];
#pragma unroll
    for (int i = 0; i < 4; ++i) {
        int c = i * 256 + tid;
        am[i] = c >> 3;  ak[i]  = (c & 7) * 4;
        bk[i] = c >> 5;  bn4[i] = (c & 31) * 4;
        adst[i] = stgAaddr + (uint32_t)(am[i] * 32 + ak[i]) * 4u;
        bdst[i] = stgBaddr + (uint32_t)(bk[i] * 128 + bn4[i]) * 4u;
    }

    float acc[4][4][4];
#pragma unroll
    for (int mt = 0; mt < 4; ++mt)
#pragma unroll
        for (int nt = 0; nt < 4; ++nt)
#pragma unroll
            for (int r = 0; r < 4; ++r) acc[mt][nt][r] = 0.0f;

    int nit = K >> 5;

    // ---- convert lambda: staging -> frag[buf] (tf32 bits) ----
    auto convert = [&](int buf) {
        uint32_t* Af = frag + buf * kFrag;
        uint32_t* Bf = Af + kAF;
#pragma unroll
        for (int i = 0; i < 4; ++i) {
            float4 a = *(const float4*)&stgA[am[i] * 32 + ak[i]];
            uint4 ua = make_uint4(f2tf32(a.x), f2tf32(a.y), f2tf32(a.z), f2tf32(a.w));
            *(uint4*)&Af[am[i] * kAP + ak[i]] = ua;
            float4 b = *(const float4*)&stgB[bk[i] * 128 + bn4[i]];
            uint4 ub = make_uint4(f2tf32(b.x), f2tf32(b.y), f2tf32(b.z), f2tf32(b.w));
            *(uint4*)&Bf[bk[i] * kBP + bn4[i]] = ub;
        }
    };
    auto stage = [&](int k0) {
#pragma unroll
        for (int i = 0; i < 4; ++i) {
            cp16(adst[i], &Ab[(size_t)am[i] * K + k0 + ak[i]]);
            cp16(bdst[i], &Bb[(size_t)(k0 + bk[i]) * N + bn4[i]]);
        }
        asm volatile("cp.async.commit_group;");
    };

    // prologue: chunk 0 -> frag0, chunk 1 -> staging
    stage(0);
    asm volatile("cp.async.wait_group 0;");
    convert(0);
    if (nit > 1) stage(32);
    __syncthreads();

    for (int it = 0; it < nit; ++it) {
        int buf = it & 1;
        const uint32_t* Ac = frag + buf * kFrag;
        const uint32_t* Bc = Ac + kAF;
#pragma unroll
        for (int ks = 0; ks < 4; ++ks) {
            uint32_t afr[4][4], bfr[4][2];
            int kk = ks * 8 + (lane & 3);
            int mrow = wm * 64 + (lane >> 2);
#pragma unroll
            for (int mt = 0; mt < 4; ++mt) {
                int m0 = mrow + mt * 16;
                afr[mt][0] = Ac[m0 * kAP + kk];
                afr[mt][1] = Ac[(m0 + 8) * kAP + kk];
                afr[mt][2] = Ac[m0 * kAP + kk + 4];
                afr[mt][3] = Ac[(m0 + 8) * kAP + kk + 4];
            }
            int ncol = wn * 32 + (lane >> 2);
#pragma unroll
            for (int nt = 0; nt < 4; ++nt) {
                int n0 = ncol + nt * 8;
                bfr[nt][0] = Bc[kk * kBP + n0];
                bfr[nt][1] = Bc[(kk + 4) * kBP + n0];
            }
#pragma unroll
            for (int mt = 0; mt < 4; ++mt)
#pragma unroll
                for (int nt = 0; nt < 4; ++nt)
                    mma_tf32(acc[mt][nt], afr[mt], bfr[nt][0], bfr[nt][1]);
        }
        if (it + 1 < nit) {
            // frag[buf^1] (chunk it-1) was fully consumed before last iter's sync
            asm volatile("cp.async.wait_group 0;");
            convert(buf ^ 1);
            if (it + 2 < nit) stage((it + 2) << 5);
            __syncthreads();
        }
    }

    // epilogue
    int rb = bm * 128 + wm * 64 + (lane >> 2);
    int cb = bn * 128 + wn * 32 + (lane & 3) * 2;
#pragma unroll
    for (int mt = 0; mt < 4; ++mt) {
#pragma unroll
        for (int nt = 0; nt < 4; ++nt) {
            int r0 = rb + mt * 16;
            int c0 = cb + nt * 8;
            float b0 = bias[c0], b1 = bias[c0 + 1];
            size_t off0 = (size_t)r0 * N + c0;
            size_t off1 = (size_t)(r0 + 8) * N + c0;
            float v0 = acc[mt][nt][0] + b0, v1 = acc[mt][nt][1] + b1;
            float v2 = acc[mt][nt][2] + b0, v3 = acc[mt][nt][3] + b1;
            if (resid) {
                float2 rr0 = *(const float2*)&resid[off0];
                float2 rr1 = *(const float2*)&resid[off1];
                v0 += rr0.x; v1 += rr0.y; v2 += rr1.x; v3 += rr1.y;
            }
            *(float2*)&C[off0] = make_float2(v0, v1);
            *(float2*)&C[off1] = make_float2(v2, v3);
        }
    }
}

// ================= flash attention with TF32 MMA =================
// 128 threads (4 warps). Each warp owns 16 query rows (warp-local softmax).
// 64-key tiles; K/V pre-converted to tf32 bits at load; P staged via
// warp-private smem. O accum in fp32 C fragments.

constexpr int kKV = 68;  // pitch (floats/u32) for Ks/Vs/Ps
constexpr int kAttnSmem = (64 * kKV * 2 + 4 * 16 * kKV) * 4;  // 52224 bytes

__global__ void __launch_bounds__(128)
flash_attn_mma(const float* __restrict__ Q, const float* __restrict__ K,
               const float* __restrict__ Vv, float* __restrict__ O)
{
    extern __shared__ uint32_t asmem[];
    uint32_t* Ks = asmem;                 // [64][kKV] tf32 bits
    uint32_t* Vs = asmem + 64 * kKV;      // [64][kKV] tf32 bits
    float*    Ps = (float*)(asmem + 2 * 64 * kKV) + (threadIdx.x >> 5) * 16 * kKV;

    int tid = threadIdx.x, lane = tid & 31, w = tid >> 5;
    int g = lane >> 2, tg = lane & 3;
    int bh = blockIdx.y;
    int b  = bh >> 4;
    int h  = bh & 15;
    int q0 = blockIdx.x * 64;
    size_t base = ((size_t)b * kL) * kD + (size_t)h * kDH;
    int rlo = q0 + w * 16 + g;            // global query row (low half)

    // Q fragments (resident for all key tiles)
    uint32_t qf[8][4];
    {
        const float* Qp = Q + base + (size_t)rlo * kD;
#pragma unroll
        for (int ks = 0; ks < 8; ++ks) {
            int kk = ks * 8 + tg;
            qf[ks][0] = f2tf32(Qp[kk]);
            qf[ks][1] = f2tf32(Qp[(size_t)8 * kD + kk]);
            qf[ks][2] = f2tf32(Qp[kk + 4]);
            qf[ks][3] = f2tf32(Qp[(size_t)8 * kD + kk + 4]);
        }
    }

    float of[8][4];
#pragma unroll
    for (int nt = 0; nt < 8; ++nt)
#pragma unroll
        for (int e = 0; e < 4; ++e) of[nt][e] = 0.0f;
    float mlo = -1e30f, mhi = -1e30f, llo = 0.0f, lhi = 0.0f;

    int nkt = blockIdx.x + 1;
    for (int kt = 0; kt < nkt; ++kt) {
        int k0 = kt * 64;
        __syncthreads();    // all warps done with previous Ks/Vs
        // load + convert K,V tile (64 rows x 64 dh)
#pragma unroll
        for (int i = 0; i < 8; ++i) {
            int c = i * 128 + tid;
            int row = c >> 4, f4 = (c & 15) * 4;
            float4 kv = *(const float4*)&K[base + (size_t)(k0 + row) * kD + f4];
            uint4 uk = make_uint4(f2tf32(kv.x), f2tf32(kv.y), f2tf32(kv.z), f2tf32(kv.w));
            *(uint4*)&Ks[row * kKV + f4] = uk;
            float4 vv = *(const float4*)&Vv[base + (size_t)(k0 + row) * kD + f4];
            uint4 uv = make_uint4(f2tf32(vv.x), f2tf32(vv.y), f2tf32(vv.z), f2tf32(vv.w));
            *(uint4*)&Vs[row * kKV + f4] = uv;
        }
        __syncthreads();

        // S = Q @ K^T   (16q x 64key per warp)
        float s[8][4];
#pragma unroll
        for (int nt = 0; nt < 8; ++nt)
#pragma unroll
            for (int e = 0; e < 4; ++e) s[nt][e] = 0.0f;
#pragma unroll
        for (int ks = 0; ks < 8; ++ks) {
            int kk = ks * 8 + tg;
#pragma unroll
            for (int nt = 0; nt < 8; ++nt) {
                int n0 = nt * 8 + g;
                uint32_t b0 = Ks[n0 * kKV + kk];
                uint32_t b1 = Ks[n0 * kKV + kk + 4];
                mma_tf32(s[nt], qf[ks], b0, b1);
            }
        }

        // scale + causal mask + online softmax (warp-local rows)
        bool diag = (kt == blockIdx.x);
        float rmlo = -1e30f, rmhi = -1e30f;
#pragma unroll
        for (int nt = 0; nt < 8; ++nt) {
#pragma unroll
            for (int e = 0; e < 4; ++e) {
                float v = s[nt][e] * 0.125f;
                if (diag) {
                    int key = k0 + nt * 8 + 2 * tg + (e & 1);
                    int row = (e < 2) ? rlo : rlo + 8;
                    if (key > row) v = -1e30f;
                }
                s[nt][e] = v;
                if (e < 2) rmlo = fmaxf(rmlo, v); else rmhi = fmaxf(rmhi, v);
            }
        }
        rmlo = fmaxf(rmlo, __shfl_xor_sync(0xffffffffu, rmlo, 1));
        rmlo = fmaxf(rmlo, __shfl_xor_sync(0xffffffffu, rmlo, 2));
        rmhi = fmaxf(rmhi, __shfl_xor_sync(0xffffffffu, rmhi, 1));
        rmhi = fmaxf(rmhi, __shfl_xor_sync(0xffffffffu, rmhi, 2));
        float mnlo = fmaxf(mlo, rmlo), mnhi = fmaxf(mhi, rmhi);
        float clo = __expf(mlo - mnlo), chi = __expf(mhi - mnhi);
        mlo = mnlo; mhi = mnhi;

        float rslo = 0.0f, rshi = 0.0f;
#pragma unroll
        for (int nt = 0; nt < 8; ++nt) {
            float p0 = __expf(s[nt][0] - mlo);
            float p1 = __expf(s[nt][1] - mlo);
            float p2 = __expf(s[nt][2] - mhi);
            float p3 = __expf(s[nt][3] - mhi);
            rslo += p0 + p1; rshi += p2 + p3;
            int col = nt * 8 + 2 * tg;
            *(float2*)&Ps[g * kKV + col]       = make_float2(p0, p1);
            *(float2*)&Ps[(g + 8) * kKV + col] = make_float2(p2, p3);
        }
        rslo += __shfl_xor_sync(0xffffffffu, rslo, 1);
        rslo += __shfl_xor_sync(0xffffffffu, rslo, 2);
        rshi += __shfl_xor_sync(0xffffffffu, rshi, 1);
        rshi += __shfl_xor_sync(0xffffffffu, rshi, 2);
        llo = llo * clo + rslo;
        lhi = lhi * chi + rshi;
#pragma unroll
        for (int nt = 0; nt < 8; ++nt) {
            of[nt][0] *= clo; of[nt][1] *= clo;
            of[nt][2] *= chi; of[nt][3] *= chi;
        }
        __syncwarp();

        // O += P @ V   (k-dim = 64 keys, n-dim = 64 dh)
#pragma unroll
        for (int ks = 0; ks < 8; ++ks) {
            int kk = ks * 8 + tg;
            uint32_t pa[4];
            pa[0] = f2tf32(Ps[g * kKV + kk]);
            pa[1] = f2tf32(Ps[(g + 8) * kKV + kk]);
            pa[2] = f2tf32(Ps[g * kKV + kk + 4]);
            pa[3] = f2tf32(Ps[(g + 8) * kKV + kk + 4]);
#pragma unroll
            for (int nt = 0; nt < 8; ++nt) {
                int n0 = nt * 8 + g;
                uint32_t b0 = Vs[kk * kKV + n0];
                uint32_t b1 = Vs[(kk + 4) * kKV + n0];
                mma_tf32(of[nt], pa, b0, b1);
            }
        }
    }

    // epilogue
    float ilo = 1.0f / llo, ihi = 1.0f / lhi;
#pragma unroll
    for (int nt = 0; nt < 8; ++nt) {
        int col = nt * 8 + 2 * tg;
        size_t off0 = base + (size_t)rlo * kD + col;
        size_t off1 = base + (size_t)(rlo + 8) * kD + col;
        *(float2*)&O[off0] = make_float2(of[nt][0] * ilo, of[nt][1] * ilo);
        *(float2*)&O[off1] = make_float2(of[nt][2] * ihi, of[nt][3] * ihi);
    }
}

// ---------------- host launcher ----------------
static void launch_gemm(const float* A, const float* B, const float* bias,
                        const float* resid, float* C, int M, int N, int K)
{
    dim3 grid(N / 128, M / 128);
    gemm_tf32_kernel<<<grid, 256, kGemmSmem>>>(A, B, bias, resid, C, M, N, K);
}

extern "C" void kernel_launch(void* const* d_in, const int* in_sizes, int n_in,
                              void* d_out, int out_size)
{
    const int*   ids    = (const int*)  d_in[0];
    const float* embed  = (const float*)d_in[1];
    const float* Wq     = (const float*)d_in[2];
    const float* bq     = (const float*)d_in[3];
    const float* Wk     = (const float*)d_in[4];
    const float* bk     = (const float*)d_in[5];
    const float* Wv     = (const float*)d_in[6];
    const float* bv     = (const float*)d_in[7];
    const float* Wo     = (const float*)d_in[8];
    const float* bo     = (const float*)d_in[9];
    const float* Wproj  = (const float*)d_in[10];
    const float* bproj  = (const float*)d_in[11];
    const float* Wup    = (const float*)d_in[12];
    const float* bup    = (const float*)d_in[13];
    const float* Wdown  = (const float*)d_in[14];
    const float* bdown  = (const float*)d_in[15];
    const float* gammas = (const float*)d_in[16];
    const float* Wlog   = (const float*)d_in[17];
    const float* blog   = (const float*)d_in[18];
    float* out = (float*)d_out;

    float *x, *h, *q, *k, *v, *att, *proj, *up;
    cudaGetSymbolAddress((void**)&x,    g_x);
    cudaGetSymbolAddress((void**)&h,    g_h);
    cudaGetSymbolAddress((void**)&q,    g_q);
    cudaGetSymbolAddress((void**)&k,    g_k);
    cudaGetSymbolAddress((void**)&v,    g_v);
    cudaGetSymbolAddress((void**)&att,  g_att);
    cudaGetSymbolAddress((void**)&proj, g_proj);
    cudaGetSymbolAddress((void**)&up,   g_up);

    cudaFuncSetAttribute(gemm_tf32_kernel,
                         cudaFuncAttributeMaxDynamicSharedMemorySize, kGemmSmem);
    cudaFuncSetAttribute(flash_attn_mma,
                         cudaFuncAttributeMaxDynamicSharedMemorySize, kAttnSmem);

    embed_pe_kernel<<<kBL, 256>>>(ids, embed, x);

    for (int i = 0; i < kNL; ++i) {
        rmsnorm_kernel<<<kBL, 256>>>(x, gammas + (size_t)(2 * i) * kD, h);
        launch_gemm(h, Wq + (size_t)i * kD * kD, bq + (size_t)i * kD, nullptr, q, kBL, kD, kD);
        launch_gemm(h, Wk + (size_t)i * kD * kD, bk + (size_t)i * kD, nullptr, k, kBL, kD, kD);
        launch_gemm(h, Wv + (size_t)i * kD * kD, bv + (size_t)i * kD, nullptr, v, kBL, kD, kD);
        flash_attn_mma<<<dim3(kL / 64, kB * kH), 128, kAttnSmem>>>(q, k, v, att);
        launch_gemm(att, Wo + (size_t)i * kD * kD, bo + (size_t)i * kD, x, x, kBL, kD, kD);
        rmsnorm_kernel<<<kBL, 256>>>(x, gammas + (size_t)(2 * i + 1) * kD, h);
        launch_gemm(h, Wproj + (size_t)i * kD * kD2, bproj + (size_t)i * kD2, nullptr, proj, kBL, kD2, kD);
        launch_gemm(h, Wup + (size_t)i * kD * kD2, bup + (size_t)i * kD2, nullptr, up, kBL, kD2, kD);
        silu_gate_kernel<<<((size_t)kBL * kD2) / (256 * 4), 256>>>(proj, up);
        launch_gemm(proj, Wdown + (size_t)i * kD2 * kD, bdown + (size_t)i * kD, x, x, kBL, kD, kD2);
    }
    launch_gemm(x, Wlog, blog, nullptr, out, kBL, kV, kD);
}

// round 4
// speedup vs baseline: 1.5877x; 1.5877x over previous
#include <cuda_runtime.h>
#include <math.h>
#include <stdint.h>

// ---------------- problem constants ----------------
constexpr int kNL = 4;
constexpr int kD  = 1024;
constexpr int kD2 = 2048;
constexpr int kH  = 16;
constexpr int kDH = 64;
constexpr int kV  = 32000;
constexpr int kB  = 2;
constexpr int kL  = 2048;
constexpr int kBL = kB * kL;   // 4096
#define EPSF 1e-6f

// ---------------- scratch (device globals; no allocation allowed) ----------------
__device__ float g_x[kBL * kD];
__device__ float g_h[kBL * kD];
__device__ float g_q[kBL * kD];
__device__ float g_k[kBL * kD];
__device__ float g_v[kBL * kD];
__device__ float g_att[kBL * kD];
__device__ float g_proj[(size_t)kBL * kD2];
__device__ float g_up[(size_t)kBL * kD2];

// tf32-converted weights (u32 bits). Layout: q,k,v,o (4 x 4M), proj (8M),
// up (8M), down (8M), logits (32.768M)  => 72.768M u32 total (~291MB)
constexpr size_t kWq   = 0;
constexpr size_t kWk   = kWq   + (size_t)kNL * kD * kD;
constexpr size_t kWv   = kWk   + (size_t)kNL * kD * kD;
constexpr size_t kWo   = kWv   + (size_t)kNL * kD * kD;
constexpr size_t kWpj  = kWo   + (size_t)kNL * kD * kD;
constexpr size_t kWup  = kWpj  + (size_t)kNL * kD * kD2;
constexpr size_t kWdn  = kWup  + (size_t)kNL * kD * kD2;
constexpr size_t kWlg  = kWdn  + (size_t)kNL * kD2 * kD;
constexpr size_t kWTot = kWlg  + (size_t)kD * kV;
__device__ uint32_t g_wtf[kWTot];

// ---------------- small helpers ----------------
__device__ __forceinline__ uint32_t f2tf32(float f) {
    uint32_t u;
    asm("cvt.rna.tf32.f32 %0, %1;" : "=r"(u) : "f"(f));
    return u;
}
__device__ __forceinline__ float rnd_tf32(float f) {
    return __uint_as_float(f2tf32(f));
}
__device__ __forceinline__ void mma_tf32(float* c, const uint32_t* a, uint32_t b0, uint32_t b1) {
    asm volatile(
        "mma.sync.aligned.m16n8k8.row.col.f32.tf32.tf32.f32 "
        "{%0,%1,%2,%3}, {%4,%5,%6,%7}, {%8,%9}, {%0,%1,%2,%3};"
        : "+f"(c[0]), "+f"(c[1]), "+f"(c[2]), "+f"(c[3])
        : "r"(a[0]), "r"(a[1]), "r"(a[2]), "r"(a[3]), "r"(b0), "r"(b1));
}
__device__ __forceinline__ void cp16(uint32_t dst, const void* src) {
    asm volatile("cp.async.cg.shared.global [%0], [%1], 16;" :: "r"(dst), "l"(src));
}

// ---------------- bulk tf32 convert (weights / logits activations) ----------------
__global__ void cvt_tf32_kernel(const float* __restrict__ in,
                                uint32_t* __restrict__ out, int n4)
{
    int i = blockIdx.x * blockDim.x + threadIdx.x;
    if (i >= n4) return;
    float4 v = ((const float4*)in)[i];
    ((uint4*)out)[i] = make_uint4(f2tf32(v.x), f2tf32(v.y), f2tf32(v.z), f2tf32(v.w));
}

// ---------------- embed + positional encoding ----------------
__global__ void embed_pe_kernel(const int* __restrict__ ids,
                                const float* __restrict__ embed,
                                float* __restrict__ x)
{
    int row = blockIdx.x;
    int l   = row % kL;
    int id  = ids[row];
    int d0  = threadIdx.x * 4;
    float4 ev = *(const float4*)&embed[(size_t)id * kD + d0];
    float out[4] = {ev.x, ev.y, ev.z, ev.w};
    const float negc = -0.0089944731f;   // -log(10000)/1024 in fp32
#pragma unroll
    for (int t = 0; t < 4; ++t) {
        int d  = d0 + t;
        int i2 = (d >> 1) * 2;
        float freq = expf((float)i2 * negc);
        float a    = (float)l * freq;
        out[t] += (d & 1) ? cosf(a) : sinf(a);
    }
    *(float4*)&x[(size_t)row * kD + d0] = make_float4(out[0], out[1], out[2], out[3]);
}

// ---------------- rmsnorm (emits tf32-rounded values) ----------------
__global__ void rmsnorm_kernel(const float* __restrict__ x,
                               const float* __restrict__ gamma,
                               float* __restrict__ y)
{
    int row = blockIdx.x;
    const float* xr = x + (size_t)row * kD;
    int d0 = threadIdx.x * 4;
    float4 v = *(const float4*)&xr[d0];
    float ss = v.x * v.x + v.y * v.y + v.z * v.z + v.w * v.w;
#pragma unroll
    for (int off = 16; off; off >>= 1)
        ss += __shfl_xor_sync(0xffffffffu, ss, off);
    __shared__ float ws[8];
    int lane = threadIdx.x & 31, w = threadIdx.x >> 5;
    if (lane == 0) ws[w] = ss;
    __syncthreads();
    if (w == 0) {
        float t = (lane < 8) ? ws[lane] : 0.0f;
#pragma unroll
        for (int off = 4; off; off >>= 1)
            t += __shfl_xor_sync(0xffffffffu, t, off);
        if (lane == 0) ws[0] = t;
    }
    __syncthreads();
    float scale = rsqrtf(ws[0] / (float)kD + EPSF);
    float4 g = *(const float4*)&gamma[d0];
    float4 o = make_float4(rnd_tf32(v.x * scale * g.x), rnd_tf32(v.y * scale * g.y),
                           rnd_tf32(v.z * scale * g.z), rnd_tf32(v.w * scale * g.w));
    *(float4*)&y[(size_t)row * kD + d0] = o;
}

// ---------------- silu gate (emits tf32-rounded values) ----------------
__global__ void silu_gate_kernel(float* __restrict__ proj,
                                 const float* __restrict__ up)
{
    size_t i = ((size_t)blockIdx.x * blockDim.x + threadIdx.x) * 4;
    float4 p = *(float4*)&proj[i];
    float4 u = *(const float4*)&up[i];
    float t0 = p.x * u.x, t1 = p.y * u.y, t2 = p.z * u.z, t3 = p.w * u.w;
    p.x = rnd_tf32(t0 / (1.0f + __expf(-t0)));
    p.y = rnd_tf32(t1 / (1.0f + __expf(-t1)));
    p.z = rnd_tf32(t2 / (1.0f + __expf(-t2)));
    p.w = rnd_tf32(t3 / (1.0f + __expf(-t3)));
    *(float4*)&proj[i] = p;
}

// ================= TF32 tensor-core GEMM (R2 pipeline, zero in-kernel cvt) ==========
// A: fp32 values pre-rounded to tf32 by producers. B: pre-converted tf32 bits.
// 128x128x32 tile, 8 warps (2x4), 64x32 warp tile, m16n8k8, cp.async double buffer.

constexpr int kAPitch = 36;
constexpr int kBPitch = 132;
constexpr int kASz = 128 * kAPitch;
constexpr int kBSz = 32 * kBPitch;
constexpr int kGemmSmem = 2 * (kASz + kBSz) * 4;   // 70656 bytes

__global__ void __launch_bounds__(256, 2)
gemm_tf32_kernel(const float* __restrict__ A, const uint32_t* __restrict__ Bw,
                 const float* __restrict__ bias, const float* __restrict__ resid,
                 float* __restrict__ C, int M, int N, int K)
{
    extern __shared__ uint32_t sm[];
    uint32_t* As = sm;                       // [2][128][kAPitch]
    uint32_t* Bs = sm + 2 * kASz;            // [2][32][kBPitch]
    uint32_t asBase = (uint32_t)__cvta_generic_to_shared(As);
    uint32_t bsBase = (uint32_t)__cvta_generic_to_shared(Bs);

    int tid  = threadIdx.x;
    int lane = tid & 31;
    int warp = tid >> 5;
    int wm = warp >> 2;
    int wn = warp & 3;
    int bm = blockIdx.y, bn = blockIdx.x;

    const float*    Ab = A  + (size_t)bm * 128 * K;
    const uint32_t* Bb = Bw + (size_t)bn * 128;

    int am[4], ak[4], bk[4], bn4[4];
    uint32_t adst[4], bdst[4];
#pragma unroll
    for (int i = 0; i < 4; ++i) {
        int c = i * 256 + tid;
        am[i] = c >> 3;            ak[i]  = (c & 7) * 4;
        bk[i] = c >> 5;            bn4[i] = (c & 31) * 4;
        adst[i] = asBase + (uint32_t)(am[i] * kAPitch + ak[i]) * 4u;
        bdst[i] = bsBase + (uint32_t)(bk[i] * kBPitch + bn4[i]) * 4u;
    }

    float acc[4][4][4];
#pragma unroll
    for (int mt = 0; mt < 4; ++mt)
#pragma unroll
        for (int nt = 0; nt < 4; ++nt)
#pragma unroll
            for (int r = 0; r < 4; ++r) acc[mt][nt][r] = 0.0f;

    int nit = K >> 5;

#pragma unroll
    for (int i = 0; i < 4; ++i) {
        cp16(adst[i], &Ab[(size_t)am[i] * K + ak[i]]);
        cp16(bdst[i], &Bb[(size_t)bk[i] * N + bn4[i]]);
    }
    asm volatile("cp.async.commit_group;");

    for (int it = 0; it < nit; ++it) {
        int buf = it & 1;
        if (it + 1 < nit) {
            int k0 = (it + 1) << 5;
            uint32_t boffA = (buf ^ 1) ? (uint32_t)(kASz * 4) : 0u;
            uint32_t boffB = (buf ^ 1) ? (uint32_t)(kBSz * 4) : 0u;
#pragma unroll
            for (int i = 0; i < 4; ++i) {
                cp16(adst[i] + boffA, &Ab[(size_t)am[i] * K + k0 + ak[i]]);
                cp16(bdst[i] + boffB, &Bb[(size_t)(k0 + bk[i]) * N + bn4[i]]);
            }
            asm volatile("cp.async.commit_group;");
            asm volatile("cp.async.wait_group 1;");
        } else {
            asm volatile("cp.async.wait_group 0;");
        }
        __syncthreads();

        const uint32_t* Ac = As + buf * kASz;
        const uint32_t* Bc = Bs + buf * kBSz;
#pragma unroll
        for (int ks = 0; ks < 4; ++ks) {
            uint32_t afr[4][4], bfr[4][2];
            int kk = ks * 8 + (lane & 3);
            int mrow = wm * 64 + (lane >> 2);
#pragma unroll
            for (int mt = 0; mt < 4; ++mt) {
                int m0 = mrow + mt * 16;
                afr[mt][0] = Ac[m0 * kAPitch + kk];
                afr[mt][1] = Ac[(m0 + 8) * kAPitch + kk];
                afr[mt][2] = Ac[m0 * kAPitch + kk + 4];
                afr[mt][3] = Ac[(m0 + 8) * kAPitch + kk + 4];
            }
            int ncol = wn * 32 + (lane >> 2);
#pragma unroll
            for (int nt = 0; nt < 4; ++nt) {
                int n0 = ncol + nt * 8;
                bfr[nt][0] = Bc[kk * kBPitch + n0];
                bfr[nt][1] = Bc[(kk + 4) * kBPitch + n0];
            }
#pragma unroll
            for (int mt = 0; mt < 4; ++mt)
#pragma unroll
                for (int nt = 0; nt < 4; ++nt)
                    mma_tf32(acc[mt][nt], afr[mt], bfr[nt][0], bfr[nt][1]);
        }
        __syncthreads();
    }

    int rb = bm * 128 + wm * 64 + (lane >> 2);
    int cb = bn * 128 + wn * 32 + (lane & 3) * 2;
#pragma unroll
    for (int mt = 0; mt < 4; ++mt) {
#pragma unroll
        for (int nt = 0; nt < 4; ++nt) {
            int r0 = rb + mt * 16;
            int c0 = cb + nt * 8;
            float b0 = bias[c0], b1 = bias[c0 + 1];
            size_t off0 = (size_t)r0 * N + c0;
            size_t off1 = (size_t)(r0 + 8) * N + c0;
            float v0 = acc[mt][nt][0] + b0, v1 = acc[mt][nt][1] + b1;
            float v2 = acc[mt][nt][2] + b0, v3 = acc[mt][nt][3] + b1;
            if (resid) {
                float2 rr0 = *(const float2*)&resid[off0];
                float2 rr1 = *(const float2*)&resid[off1];
                v0 += rr0.x; v1 += rr0.y; v2 += rr1.x; v3 += rr1.y;
            }
            *(float2*)&C[off0] = make_float2(v0, v1);
            *(float2*)&C[off1] = make_float2(v2, v3);
        }
    }
}

// ================= flash attention with TF32 MMA (R3, kept) =================
constexpr int kKV = 68;
constexpr int kAttnSmem = (64 * kKV * 2 + 4 * 16 * kKV) * 4;  // 52224 bytes

__global__ void __launch_bounds__(128)
flash_attn_mma(const float* __restrict__ Q, const float* __restrict__ K,
               const float* __restrict__ Vv, float* __restrict__ O)
{
    extern __shared__ uint32_t asmem[];
    uint32_t* Ks = asmem;
    uint32_t* Vs = asmem + 64 * kKV;
    float*    Ps = (float*)(asmem + 2 * 64 * kKV) + (threadIdx.x >> 5) * 16 * kKV;

    int tid = threadIdx.x, lane = tid & 31, w = tid >> 5;
    int g = lane >> 2, tg = lane & 3;
    int bh = blockIdx.y;
    int b  = bh >> 4;
    int h  = bh & 15;
    int q0 = blockIdx.x * 64;
    size_t base = ((size_t)b * kL) * kD + (size_t)h * kDH;
    int rlo = q0 + w * 16 + g;

    uint32_t qf[8][4];
    {
        const float* Qp = Q + base + (size_t)rlo * kD;
#pragma unroll
        for (int ks = 0; ks < 8; ++ks) {
            int kk = ks * 8 + tg;
            qf[ks][0] = f2tf32(Qp[kk]);
            qf[ks][1] = f2tf32(Qp[(size_t)8 * kD + kk]);
            qf[ks][2] = f2tf32(Qp[kk + 4]);
            qf[ks][3] = f2tf32(Qp[(size_t)8 * kD + kk + 4]);
        }
    }

    float of[8][4];
#pragma unroll
    for (int nt = 0; nt < 8; ++nt)
#pragma unroll
        for (int e = 0; e < 4; ++e) of[nt][e] = 0.0f;
    float mlo = -1e30f, mhi = -1e30f, llo = 0.0f, lhi = 0.0f;

    int nkt = blockIdx.x + 1;
    for (int kt = 0; kt < nkt; ++kt) {
        int k0 = kt * 64;
        __syncthreads();
#pragma unroll
        for (int i = 0; i < 8; ++i) {
            int c = i * 128 + tid;
            int row = c >> 4, f4 = (c & 15) * 4;
            float4 kv = *(const float4*)&K[base + (size_t)(k0 + row) * kD + f4];
            *(uint4*)&Ks[row * kKV + f4] =
                make_uint4(f2tf32(kv.x), f2tf32(kv.y), f2tf32(kv.z), f2tf32(kv.w));
            float4 vv = *(const float4*)&Vv[base + (size_t)(k0 + row) * kD + f4];
            *(uint4*)&Vs[row * kKV + f4] =
                make_uint4(f2tf32(vv.x), f2tf32(vv.y), f2tf32(vv.z), f2tf32(vv.w));
        }
        __syncthreads();

        float s[8][4];
#pragma unroll
        for (int nt = 0; nt < 8; ++nt)
#pragma unroll
            for (int e = 0; e < 4; ++e) s[nt][e] = 0.0f;
#pragma unroll
        for (int ks = 0; ks < 8; ++ks) {
            int kk = ks * 8 + tg;
#pragma unroll
            for (int nt = 0; nt < 8; ++nt) {
                int n0 = nt * 8 + g;
                mma_tf32(s[nt], qf[ks], Ks[n0 * kKV + kk], Ks[n0 * kKV + kk + 4]);
            }
        }

        bool diag = (kt == blockIdx.x);
        float rmlo = -1e30f, rmhi = -1e30f;
#pragma unroll
        for (int nt = 0; nt < 8; ++nt) {
#pragma unroll
            for (int e = 0; e < 4; ++e) {
                float v = s[nt][e] * 0.125f;
                if (diag) {
                    int key = k0 + nt * 8 + 2 * tg + (e & 1);
                    int row = (e < 2) ? rlo : rlo + 8;
                    if (key > row) v = -1e30f;
                }
                s[nt][e] = v;
                if (e < 2) rmlo = fmaxf(rmlo, v); else rmhi = fmaxf(rmhi, v);
            }
        }
        rmlo = fmaxf(rmlo, __shfl_xor_sync(0xffffffffu, rmlo, 1));
        rmlo = fmaxf(rmlo, __shfl_xor_sync(0xffffffffu, rmlo, 2));
        rmhi = fmaxf(rmhi, __shfl_xor_sync(0xffffffffu, rmhi, 1));
        rmhi = fmaxf(rmhi, __shfl_xor_sync(0xffffffffu, rmhi, 2));
        float mnlo = fmaxf(mlo, rmlo), mnhi = fmaxf(mhi, rmhi);
        float clo = __expf(mlo - mnlo), chi = __expf(mhi - mnhi);
        mlo = mnlo; mhi = mnhi;

        float rslo = 0.0f, rshi = 0.0f;
#pragma unroll
        for (int nt = 0; nt < 8; ++nt) {
            float p0 = __expf(s[nt][0] - mlo);
            float p1 = __expf(s[nt][1] - mlo);
            float p2 = __expf(s[nt][2] - mhi);
            float p3 = __expf(s[nt][3] - mhi);
            rslo += p0 + p1; rshi += p2 + p3;
            int col = nt * 8 + 2 * tg;
            *(float2*)&Ps[g * kKV + col]       = make_float2(p0, p1);
            *(float2*)&Ps[(g + 8) * kKV + col] = make_float2(p2, p3);
        }
        rslo += __shfl_xor_sync(0xffffffffu, rslo, 1);
        rslo += __shfl_xor_sync(0xffffffffu, rslo, 2);
        rshi += __shfl_xor_sync(0xffffffffu, rshi, 1);
        rshi += __shfl_xor_sync(0xffffffffu, rshi, 2);
        llo = llo * clo + rslo;
        lhi = lhi * chi + rshi;
#pragma unroll
        for (int nt = 0; nt < 8; ++nt) {
            of[nt][0] *= clo; of[nt][1] *= clo;
            of[nt][2] *= chi; of[nt][3] *= chi;
        }
        __syncwarp();

#pragma unroll
        for (int ks = 0; ks < 8; ++ks) {
            int kk = ks * 8 + tg;
            uint32_t pa[4];
            pa[0] = f2tf32(Ps[g * kKV + kk]);
            pa[1] = f2tf32(Ps[(g + 8) * kKV + kk]);
            pa[2] = f2tf32(Ps[g * kKV + kk + 4]);
            pa[3] = f2tf32(Ps[(g + 8) * kKV + kk + 4]);
#pragma unroll
            for (int nt = 0; nt < 8; ++nt) {
                int n0 = nt * 8 + g;
                mma_tf32(of[nt], pa, Vs[kk * kKV + n0], Vs[(kk + 4) * kKV + n0]);
            }
        }
    }

    // epilogue: normalize, tf32-round (att feeds Wo GEMM as A), store
    float ilo = 1.0f / llo, ihi = 1.0f / lhi;
#pragma unroll
    for (int nt = 0; nt < 8; ++nt) {
        int col = nt * 8 + 2 * tg;
        size_t off0 = base + (size_t)rlo * kD + col;
        size_t off1 = base + (size_t)(rlo + 8) * kD + col;
        *(float2*)&O[off0] = make_float2(rnd_tf32(of[nt][0] * ilo), rnd_tf32(of[nt][1] * ilo));
        *(float2*)&O[off1] = make_float2(rnd_tf32(of[nt][2] * ihi), rnd_tf32(of[nt][3] * ihi));
    }
}

// ---------------- host launcher ----------------
static void launch_gemm(const float* A, const uint32_t* B, const float* bias,
                        const float* resid, float* C, int M, int N, int K)
{
    dim3 grid(N / 128, M / 128);
    gemm_tf32_kernel<<<grid, 256, kGemmSmem>>>(A, B, bias, resid, C, M, N, K);
}
static void launch_cvt(const float* in, uint32_t* out, size_t n)
{
    int n4 = (int)(n / 4);
    cvt_tf32_kernel<<<(n4 + 255) / 256, 256>>>(in, out, n4);
}

extern "C" void kernel_launch(void* const* d_in, const int* in_sizes, int n_in,
                              void* d_out, int out_size)
{
    const int*   ids    = (const int*)  d_in[0];
    const float* embed  = (const float*)d_in[1];
    const float* Wq     = (const float*)d_in[2];
    const float* bq     = (const float*)d_in[3];
    const float* Wk     = (const float*)d_in[4];
    const float* bk     = (const float*)d_in[5];
    const float* Wv     = (const float*)d_in[6];
    const float* bv     = (const float*)d_in[7];
    const float* Wo     = (const float*)d_in[8];
    const float* bo     = (const float*)d_in[9];
    const float* Wproj  = (const float*)d_in[10];
    const float* bproj  = (const float*)d_in[11];
    const float* Wup    = (const float*)d_in[12];
    const float* bup    = (const float*)d_in[13];
    const float* Wdown  = (const float*)d_in[14];
    const float* bdown  = (const float*)d_in[15];
    const float* gammas = (const float*)d_in[16];
    const float* Wlog   = (const float*)d_in[17];
    const float* blog   = (const float*)d_in[18];
    float* out = (float*)d_out;

    float *x, *h, *q, *k, *v, *att, *proj, *up;
    uint32_t* wtf;
    cudaGetSymbolAddress((void**)&x,    g_x);
    cudaGetSymbolAddress((void**)&h,    g_h);
    cudaGetSymbolAddress((void**)&q,    g_q);
    cudaGetSymbolAddress((void**)&k,    g_k);
    cudaGetSymbolAddress((void**)&v,    g_v);
    cudaGetSymbolAddress((void**)&att,  g_att);
    cudaGetSymbolAddress((void**)&proj, g_proj);
    cudaGetSymbolAddress((void**)&up,   g_up);
    cudaGetSymbolAddress((void**)&wtf,  g_wtf);

    cudaFuncSetAttribute(gemm_tf32_kernel,
                         cudaFuncAttributeMaxDynamicSharedMemorySize, kGemmSmem);
    cudaFuncSetAttribute(flash_attn_mma,
                         cudaFuncAttributeMaxDynamicSharedMemorySize, kAttnSmem);

    // per-launch weight conversion (deterministic, graph-capturable)
    launch_cvt(Wq,    wtf + kWq,  (size_t)kNL * kD * kD);
    launch_cvt(Wk,    wtf + kWk,  (size_t)kNL * kD * kD);
    launch_cvt(Wv,    wtf + kWv,  (size_t)kNL * kD * kD);
    launch_cvt(Wo,    wtf + kWo,  (size_t)kNL * kD * kD);
    launch_cvt(Wproj, wtf + kWpj, (size_t)kNL * kD * kD2);
    launch_cvt(Wup,   wtf + kWup, (size_t)kNL * kD * kD2);
    launch_cvt(Wdown, wtf + kWdn, (size_t)kNL * kD2 * kD);
    launch_cvt(Wlog,  wtf + kWlg, (size_t)kD * kV);

    embed_pe_kernel<<<kBL, 256>>>(ids, embed, x);

    for (int i = 0; i < kNL; ++i) {
        rmsnorm_kernel<<<kBL, 256>>>(x, gammas + (size_t)(2 * i) * kD, h);
        launch_gemm(h, wtf + kWq + (size_t)i * kD * kD, bq + (size_t)i * kD, nullptr, q, kBL, kD, kD);
        launch_gemm(h, wtf + kWk + (size_t)i * kD * kD, bk + (size_t)i * kD, nullptr, k, kBL, kD, kD);
        launch_gemm(h, wtf + kWv + (size_t)i * kD * kD, bv + (size_t)i * kD, nullptr, v, kBL, kD, kD);
        flash_attn_mma<<<dim3(kL / 64, kB * kH), 128, kAttnSmem>>>(q, k, v, att);
        launch_gemm(att, wtf + kWo + (size_t)i * kD * kD, bo + (size_t)i * kD, x, x, kBL, kD, kD);
        rmsnorm_kernel<<<kBL, 256>>>(x, gammas + (size_t)(2 * i + 1) * kD, h);
        launch_gemm(h, wtf + kWpj + (size_t)i * kD * kD2, bproj + (size_t)i * kD2, nullptr, proj, kBL, kD2, kD);
        launch_gemm(h, wtf + kWup + (size_t)i * kD * kD2, bup + (size_t)i * kD2, nullptr, up, kBL, kD2, kD);
        silu_gate_kernel<<<((size_t)kBL * kD2) / (256 * 4), 256>>>(proj, up);
        launch_gemm(proj, wtf + kWdn + (size_t)i * kD2 * kD, bdown + (size_t)i * kD, x, x, kBL, kD, kD2);
    }
    // round x once for the logits GEMM A operand (reuse g_h as bit buffer)
    launch_cvt(x, (uint32_t*)h, (size_t)kBL * kD);
    launch_gemm(h, wtf + kWlg, blog, nullptr, out, kBL, kV, kD);
}

// round 5
// speedup vs baseline: 1.7325x; 1.0912x over previous
#include <cuda_runtime.h>
#include <math.h>
#include <stdint.h>

// ---------------- problem constants ----------------
constexpr int kNL = 4;
constexpr int kD  = 1024;
constexpr int kD2 = 2048;
constexpr int kH  = 16;
constexpr int kDH = 64;
constexpr int kV  = 32000;
constexpr int kB  = 2;
constexpr int kL  = 2048;
constexpr int kBL = kB * kL;   // 4096
#define EPSF 1e-6f

// ---------------- scratch (device globals; no allocation allowed) ----------------
__device__ float g_x[kBL * kD];
__device__ float g_h[kBL * kD];
__device__ float g_q[kBL * kD];
__device__ float g_k[kBL * kD];
__device__ float g_v[kBL * kD];
__device__ float g_att[kBL * kD];
__device__ float g_proj[(size_t)kBL * kD2];
__device__ float g_up[(size_t)kBL * kD2];

// tf32-converted + TRANSPOSED weights (u32 bits), layout [N][K] per matrix.
constexpr size_t kWq   = 0;
constexpr size_t kWk   = kWq   + (size_t)kNL * kD * kD;
constexpr size_t kWv   = kWk   + (size_t)kNL * kD * kD;
constexpr size_t kWo   = kWv   + (size_t)kNL * kD * kD;
constexpr size_t kWpj  = kWo   + (size_t)kNL * kD * kD2;
constexpr size_t kWup  = kWpj  + (size_t)kNL * kD * kD2;
constexpr size_t kWdn  = kWup  + (size_t)kNL * kD * kD2;
constexpr size_t kWlg  = kWdn  + (size_t)kNL * kD2 * kD;
constexpr size_t kWTot = kWlg  + (size_t)kD * kV;
__device__ uint32_t g_wtf[kWTot];

// ---------------- small helpers ----------------
__device__ __forceinline__ uint32_t f2tf32(float f) {
    uint32_t u;
    asm("cvt.rna.tf32.f32 %0, %1;" : "=r"(u) : "f"(f));
    return u;
}
__device__ __forceinline__ float rnd_tf32(float f) {
    return __uint_as_float(f2tf32(f));
}
__device__ __forceinline__ void mma_tf32(float* c, const uint32_t* a, uint32_t b0, uint32_t b1) {
    asm volatile(
        "mma.sync.aligned.m16n8k8.row.col.f32.tf32.tf32.f32 "
        "{%0,%1,%2,%3}, {%4,%5,%6,%7}, {%8,%9}, {%0,%1,%2,%3};"
        : "+f"(c[0]), "+f"(c[1]), "+f"(c[2]), "+f"(c[3])
        : "r"(a[0]), "r"(a[1]), "r"(a[2]), "r"(a[3]), "r"(b0), "r"(b1));
}
__device__ __forceinline__ void cp16(uint32_t dst, const void* src) {
    asm volatile("cp.async.cg.shared.global [%0], [%1], 16;" :: "r"(dst), "l"(src));
}
__device__ __forceinline__ void ldsm4(uint32_t& r0, uint32_t& r1, uint32_t& r2, uint32_t& r3,
                                      uint32_t addr) {
    asm volatile("ldmatrix.sync.aligned.m8n8.x4.shared.b16 {%0,%1,%2,%3}, [%4];"
                 : "=r"(r0), "=r"(r1), "=r"(r2), "=r"(r3) : "r"(addr));
}

// ---------------- tf32 convert + transpose: in[K][N] -> out[N][K] bits ----------------
__global__ void cvt_t_kernel(const float* __restrict__ in, uint32_t* __restrict__ out,
                             int K, int N)
{
    __shared__ uint32_t tile[32][33];
    int kb = blockIdx.y * 32, nb = blockIdx.x * 32;
    int tx = threadIdx.x & 31, ty = threadIdx.x >> 5;   // 256 threads: 8 rows/pass
#pragma unroll
    for (int r = ty; r < 32; r += 8)
        tile[r][tx] = f2tf32(in[(size_t)(kb + r) * N + nb + tx]);
    __syncthreads();
#pragma unroll
    for (int r = ty; r < 32; r += 8)
        out[(size_t)(nb + r) * K + kb + tx] = tile[tx][r];
}

// ---------------- plain tf32 convert (logits activations) ----------------
__global__ void cvt_tf32_kernel(const float* __restrict__ in,
                                uint32_t* __restrict__ out, int n4)
{
    int i = blockIdx.x * blockDim.x + threadIdx.x;
    if (i >= n4) return;
    float4 v = ((const float4*)in)[i];
    ((uint4*)out)[i] = make_uint4(f2tf32(v.x), f2tf32(v.y), f2tf32(v.z), f2tf32(v.w));
}

// ---------------- embed + positional encoding ----------------
__global__ void embed_pe_kernel(const int* __restrict__ ids,
                                const float* __restrict__ embed,
                                float* __restrict__ x)
{
    int row = blockIdx.x;
    int l   = row % kL;
    int id  = ids[row];
    int d0  = threadIdx.x * 4;
    float4 ev = *(const float4*)&embed[(size_t)id * kD + d0];
    float out[4] = {ev.x, ev.y, ev.z, ev.w};
    const float negc = -0.0089944731f;   // -log(10000)/1024 in fp32
#pragma unroll
    for (int t = 0; t < 4; ++t) {
        int d  = d0 + t;
        int i2 = (d >> 1) * 2;
        float freq = expf((float)i2 * negc);
        float a    = (float)l * freq;
        out[t] += (d & 1) ? cosf(a) : sinf(a);
    }
    *(float4*)&x[(size_t)row * kD + d0] = make_float4(out[0], out[1], out[2], out[3]);
}

// ---------------- rmsnorm (emits tf32-rounded values) ----------------
__global__ void rmsnorm_kernel(const float* __restrict__ x,
                               const float* __restrict__ gamma,
                               float* __restrict__ y)
{
    int row = blockIdx.x;
    const float* xr = x + (size_t)row * kD;
    int d0 = threadIdx.x * 4;
    float4 v = *(const float4*)&xr[d0];
    float ss = v.x * v.x + v.y * v.y + v.z * v.z + v.w * v.w;
#pragma unroll
    for (int off = 16; off; off >>= 1)
        ss += __shfl_xor_sync(0xffffffffu, ss, off);
    __shared__ float ws[8];
    int lane = threadIdx.x & 31, w = threadIdx.x >> 5;
    if (lane == 0) ws[w] = ss;
    __syncthreads();
    if (w == 0) {
        float t = (lane < 8) ? ws[lane] : 0.0f;
#pragma unroll
        for (int off = 4; off; off >>= 1)
            t += __shfl_xor_sync(0xffffffffu, t, off);
        if (lane == 0) ws[0] = t;
    }
    __syncthreads();
    float scale = rsqrtf(ws[0] / (float)kD + EPSF);
    float4 g = *(const float4*)&gamma[d0];
    float4 o = make_float4(rnd_tf32(v.x * scale * g.x), rnd_tf32(v.y * scale * g.y),
                           rnd_tf32(v.z * scale * g.z), rnd_tf32(v.w * scale * g.w));
    *(float4*)&y[(size_t)row * kD + d0] = o;
}

// ---------------- silu gate (emits tf32-rounded values) ----------------
__global__ void silu_gate_kernel(float* __restrict__ proj,
                                 const float* __restrict__ up)
{
    size_t i = ((size_t)blockIdx.x * blockDim.x + threadIdx.x) * 4;
    float4 p = *(float4*)&proj[i];
    float4 u = *(const float4*)&up[i];
    float t0 = p.x * u.x, t1 = p.y * u.y, t2 = p.z * u.z, t3 = p.w * u.w;
    p.x = rnd_tf32(t0 / (1.0f + __expf(-t0)));
    p.y = rnd_tf32(t1 / (1.0f + __expf(-t1)));
    p.z = rnd_tf32(t2 / (1.0f + __expf(-t2)));
    p.w = rnd_tf32(t3 / (1.0f + __expf(-t3)));
    *(float4*)&proj[i] = p;
}

// ================= TF32 tensor-core GEMM with LDSM fragments =================
// A[M,K] fp32 (pre-rounded), Bt[N,K] tf32 bits (transposed). Both staged to
// smem [128 rows][32 k] pitch 36 (conflict-free for ldmatrix). 128x128x32 tile,
// 8 warps (2x4), 64x32 warp tile, m16n8k8, cp.async double buffer.

constexpr int kTP   = 36;             // smem tile pitch (u32)
constexpr int kTile = 128 * kTP;      // 4608 u32 per operand per buffer
constexpr int kGemmSmem = 4 * kTile * 4;  // 73728 bytes

__global__ void __launch_bounds__(256, 2)
gemm_tf32_kernel(const float* __restrict__ A, const uint32_t* __restrict__ Bt,
                 const float* __restrict__ bias, const float* __restrict__ resid,
                 float* __restrict__ C, int M, int N, int K)
{
    extern __shared__ uint32_t sm[];
    uint32_t base = (uint32_t)__cvta_generic_to_shared(sm);
    // buffer b: A at b*2*kTile, B at b*2*kTile + kTile   (u32 units)

    int tid  = threadIdx.x;
    int lane = tid & 31;
    int warp = tid >> 5;
    int wm = warp >> 2;
    int wn = warp & 3;
    int bm = blockIdx.y, bn = blockIdx.x;

    const float*    Ab = A  + (size_t)bm * 128 * K;
    const uint32_t* Bb = Bt + (size_t)(bn * 128) * K;

    // cp.async decomposition: 4 chunks per operand (row = c>>3, k-sub = (c&7)*4)
    int rw[4], cl[4];
    uint32_t dstA[4], dstB[4];
#pragma unroll
    for (int i = 0; i < 4; ++i) {
        int c = i * 256 + tid;
        rw[i] = c >> 3;
        cl[i] = (c & 7) * 4;
        dstA[i] = base + (uint32_t)(rw[i] * kTP + cl[i]) * 4u;
        dstB[i] = base + (uint32_t)(kTile + rw[i] * kTP + cl[i]) * 4u;
    }

    // ldmatrix per-thread base addresses
    int q  = lane >> 3;      // matrix index within .x4
    int r8 = lane & 7;       // row within matrix
    uint32_t aAddr = base + (uint32_t)(((wm * 64 + (q & 1) * 8 + r8) * kTP + (q >> 1) * 4)) * 4u;
    uint32_t bAddr = base + (uint32_t)((kTile + (wn * 32 + (q >> 1) * 8 + r8) * kTP + (q & 1) * 4)) * 4u;

    float acc[4][4][4];
#pragma unroll
    for (int mt = 0; mt < 4; ++mt)
#pragma unroll
        for (int nt = 0; nt < 4; ++nt)
#pragma unroll
            for (int r = 0; r < 4; ++r) acc[mt][nt][r] = 0.0f;

    int nit = K >> 5;

#pragma unroll
    for (int i = 0; i < 4; ++i) {
        cp16(dstA[i], &Ab[(size_t)rw[i] * K + cl[i]]);
        cp16(dstB[i], &Bb[(size_t)rw[i] * K + cl[i]]);
    }
    asm volatile("cp.async.commit_group;");

    for (int it = 0; it < nit; ++it) {
        int buf = it & 1;
        uint32_t bufoff = buf ? (uint32_t)(2 * kTile * 4) : 0u;
        if (it + 1 < nit) {
            int k0 = (it + 1) << 5;
            uint32_t noff = (buf ^ 1) ? (uint32_t)(2 * kTile * 4) : 0u;
#pragma unroll
            for (int i = 0; i < 4; ++i) {
                cp16(dstA[i] + noff, &Ab[(size_t)rw[i] * K + k0 + cl[i]]);
                cp16(dstB[i] + noff, &Bb[(size_t)rw[i] * K + k0 + cl[i]]);
            }
            asm volatile("cp.async.commit_group;");
            asm volatile("cp.async.wait_group 1;");
        } else {
            asm volatile("cp.async.wait_group 0;");
        }
        __syncthreads();

#pragma unroll
        for (int ks = 0; ks < 4; ++ks) {
            uint32_t afr[4][4], bfr[4][2];
#pragma unroll
            for (int mt = 0; mt < 4; ++mt)
                ldsm4(afr[mt][0], afr[mt][1], afr[mt][2], afr[mt][3],
                      aAddr + bufoff + (uint32_t)((mt * 16 * kTP + ks * 8) * 4));
#pragma unroll
            for (int ntp = 0; ntp < 2; ++ntp)
                ldsm4(bfr[2 * ntp][0], bfr[2 * ntp][1], bfr[2 * ntp + 1][0], bfr[2 * ntp + 1][1],
                      bAddr + bufoff + (uint32_t)((ntp * 16 * kTP + ks * 8) * 4));
#pragma unroll
            for (int mt = 0; mt < 4; ++mt)
#pragma unroll
                for (int nt = 0; nt < 4; ++nt)
                    mma_tf32(acc[mt][nt], afr[mt], bfr[nt][0], bfr[nt][1]);
        }
        __syncthreads();
    }

    // epilogue: bias (+resid) and store
    int rb = bm * 128 + wm * 64 + (lane >> 2);
    int cb = bn * 128 + wn * 32 + (lane & 3) * 2;
#pragma unroll
    for (int mt = 0; mt < 4; ++mt) {
#pragma unroll
        for (int nt = 0; nt < 4; ++nt) {
            int r0 = rb + mt * 16;
            int c0 = cb + nt * 8;
            float b0 = bias[c0], b1 = bias[c0 + 1];
            size_t off0 = (size_t)r0 * N + c0;
            size_t off1 = (size_t)(r0 + 8) * N + c0;
            float v0 = acc[mt][nt][0] + b0, v1 = acc[mt][nt][1] + b1;
            float v2 = acc[mt][nt][2] + b0, v3 = acc[mt][nt][3] + b1;
            if (resid) {
                float2 rr0 = *(const float2*)&resid[off0];
                float2 rr1 = *(const float2*)&resid[off1];
                v0 += rr0.x; v1 += rr0.y; v2 += rr1.x; v3 += rr1.y;
            }
            *(float2*)&C[off0] = make_float2(v0, v1);
            *(float2*)&C[off1] = make_float2(v2, v3);
        }
    }
}

// ================= flash attention with TF32 MMA (unchanged) =================
constexpr int kKV = 68;
constexpr int kAttnSmem = (64 * kKV * 2 + 4 * 16 * kKV) * 4;  // 52224 bytes

__global__ void __launch_bounds__(128)
flash_attn_mma(const float* __restrict__ Q, const float* __restrict__ K,
               const float* __restrict__ Vv, float* __restrict__ O)
{
    extern __shared__ uint32_t asmem[];
    uint32_t* Ks = asmem;
    uint32_t* Vs = asmem + 64 * kKV;
    float*    Ps = (float*)(asmem + 2 * 64 * kKV) + (threadIdx.x >> 5) * 16 * kKV;

    int tid = threadIdx.x, lane = tid & 31, w = tid >> 5;
    int g = lane >> 2, tg = lane & 3;
    int bh = blockIdx.y;
    int b  = bh >> 4;
    int h  = bh & 15;
    int q0 = blockIdx.x * 64;
    size_t base = ((size_t)b * kL) * kD + (size_t)h * kDH;
    int rlo = q0 + w * 16 + g;

    uint32_t qf[8][4];
    {
        const float* Qp = Q + base + (size_t)rlo * kD;
#pragma unroll
        for (int ks = 0; ks < 8; ++ks) {
            int kk = ks * 8 + tg;
            qf[ks][0] = f2tf32(Qp[kk]);
            qf[ks][1] = f2tf32(Qp[(size_t)8 * kD + kk]);
            qf[ks][2] = f2tf32(Qp[kk + 4]);
            qf[ks][3] = f2tf32(Qp[(size_t)8 * kD + kk + 4]);
        }
    }

    float of[8][4];
#pragma unroll
    for (int nt = 0; nt < 8; ++nt)
#pragma unroll
        for (int e = 0; e < 4; ++e) of[nt][e] = 0.0f;
    float mlo = -1e30f, mhi = -1e30f, llo = 0.0f, lhi = 0.0f;

    int nkt = blockIdx.x + 1;
    for (int kt = 0; kt < nkt; ++kt) {
        int k0 = kt * 64;
        __syncthreads();
#pragma unroll
        for (int i = 0; i < 8; ++i) {
            int c = i * 128 + tid;
            int row = c >> 4, f4 = (c & 15) * 4;
            float4 kv = *(const float4*)&K[base + (size_t)(k0 + row) * kD + f4];
            *(uint4*)&Ks[row * kKV + f4] =
                make_uint4(f2tf32(kv.x), f2tf32(kv.y), f2tf32(kv.z), f2tf32(kv.w));
            float4 vv = *(const float4*)&Vv[base + (size_t)(k0 + row) * kD + f4];
            *(uint4*)&Vs[row * kKV + f4] =
                make_uint4(f2tf32(vv.x), f2tf32(vv.y), f2tf32(vv.z), f2tf32(vv.w));
        }
        __syncthreads();

        float s[8][4];
#pragma unroll
        for (int nt = 0; nt < 8; ++nt)
#pragma unroll
            for (int e = 0; e < 4; ++e) s[nt][e] = 0.0f;
#pragma unroll
        for (int ks = 0; ks < 8; ++ks) {
            int kk = ks * 8 + tg;
#pragma unroll
            for (int nt = 0; nt < 8; ++nt) {
                int n0 = nt * 8 + g;
                mma_tf32(s[nt], qf[ks], Ks[n0 * kKV + kk], Ks[n0 * kKV + kk + 4]);
            }
        }

        bool diag = (kt == blockIdx.x);
        float rmlo = -1e30f, rmhi = -1e30f;
#pragma unroll
        for (int nt = 0; nt < 8; ++nt) {
#pragma unroll
            for (int e = 0; e < 4; ++e) {
                float v = s[nt][e] * 0.125f;
                if (diag) {
                    int key = k0 + nt * 8 + 2 * tg + (e & 1);
                    int row = (e < 2) ? rlo : rlo + 8;
                    if (key > row) v = -1e30f;
                }
                s[nt][e] = v;
                if (e < 2) rmlo = fmaxf(rmlo, v); else rmhi = fmaxf(rmhi, v);
            }
        }
        rmlo = fmaxf(rmlo, __shfl_xor_sync(0xffffffffu, rmlo, 1));
        rmlo = fmaxf(rmlo, __shfl_xor_sync(0xffffffffu, rmlo, 2));
        rmhi = fmaxf(rmhi, __shfl_xor_sync(0xffffffffu, rmhi, 1));
        rmhi = fmaxf(rmhi, __shfl_xor_sync(0xffffffffu, rmhi, 2));
        float mnlo = fmaxf(mlo, rmlo), mnhi = fmaxf(mhi, rmhi);
        float clo = __expf(mlo - mnlo), chi = __expf(mhi - mnhi);
        mlo = mnlo; mhi = mnhi;

        float rslo = 0.0f, rshi = 0.0f;
#pragma unroll
        for (int nt = 0; nt < 8; ++nt) {
            float p0 = __expf(s[nt][0] - mlo);
            float p1 = __expf(s[nt][1] - mlo);
            float p2 = __expf(s[nt][2] - mhi);
            float p3 = __expf(s[nt][3] - mhi);
            rslo += p0 + p1; rshi += p2 + p3;
            int col = nt * 8 + 2 * tg;
            *(float2*)&Ps[g * kKV + col]       = make_float2(p0, p1);
            *(float2*)&Ps[(g + 8) * kKV + col] = make_float2(p2, p3);
        }
        rslo += __shfl_xor_sync(0xffffffffu, rslo, 1);
        rslo += __shfl_xor_sync(0xffffffffu, rslo, 2);
        rshi += __shfl_xor_sync(0xffffffffu, rshi, 1);
        rshi += __shfl_xor_sync(0xffffffffu, rshi, 2);
        llo = llo * clo + rslo;
        lhi = lhi * chi + rshi;
#pragma unroll
        for (int nt = 0; nt < 8; ++nt) {
            of[nt][0] *= clo; of[nt][1] *= clo;
            of[nt][2] *= chi; of[nt][3] *= chi;
        }
        __syncwarp();

#pragma unroll
        for (int ks = 0; ks < 8; ++ks) {
            int kk = ks * 8 + tg;
            uint32_t pa[4];
            pa[0] = f2tf32(Ps[g * kKV + kk]);
            pa[1] = f2tf32(Ps[(g + 8) * kKV + kk]);
            pa[2] = f2tf32(Ps[g * kKV + kk + 4]);
            pa[3] = f2tf32(Ps[(g + 8) * kKV + kk + 4]);
#pragma unroll
            for (int nt = 0; nt < 8; ++nt) {
                int n0 = nt * 8 + g;
                mma_tf32(of[nt], pa, Vs[kk * kKV + n0], Vs[(kk + 4) * kKV + n0]);
            }
        }
    }

    float ilo = 1.0f / llo, ihi = 1.0f / lhi;
#pragma unroll
    for (int nt = 0; nt < 8; ++nt) {
        int col = nt * 8 + 2 * tg;
        size_t off0 = base + (size_t)rlo * kD + col;
        size_t off1 = base + (size_t)(rlo + 8) * kD + col;
        *(float2*)&O[off0] = make_float2(rnd_tf32(of[nt][0] * ilo), rnd_tf32(of[nt][1] * ilo));
        *(float2*)&O[off1] = make_float2(rnd_tf32(of[nt][2] * ihi), rnd_tf32(of[nt][3] * ihi));
    }
}

// ---------------- host launcher ----------------
static void launch_gemm(const float* A, const uint32_t* Bt, const float* bias,
                        const float* resid, float* C, int M, int N, int K)
{
    dim3 grid(N / 128, M / 128);
    gemm_tf32_kernel<<<grid, 256, kGemmSmem>>>(A, Bt, bias, resid, C, M, N, K);
}
static void launch_cvt_t(const float* in, uint32_t* out, int K, int N)
{
    dim3 grid(N / 32, K / 32);
    cvt_t_kernel<<<grid, 256>>>(in, out, K, N);
}

extern "C" void kernel_launch(void* const* d_in, const int* in_sizes, int n_in,
                              void* d_out, int out_size)
{
    const int*   ids    = (const int*)  d_in[0];
    const float* embed  = (const float*)d_in[1];
    const float* Wq     = (const float*)d_in[2];
    const float* bq     = (const float*)d_in[3];
    const float* Wk     = (const float*)d_in[4];
    const float* bk     = (const float*)d_in[5];
    const float* Wv     = (const float*)d_in[6];
    const float* bv     = (const float*)d_in[7];
    const float* Wo     = (const float*)d_in[8];
    const float* bo     = (const float*)d_in[9];
    const float* Wproj  = (const float*)d_in[10];
    const float* bproj  = (const float*)d_in[11];
    const float* Wup    = (const float*)d_in[12];
    const float* bup    = (const float*)d_in[13];
    const float* Wdown  = (const float*)d_in[14];
    const float* bdown  = (const float*)d_in[15];
    const float* gammas = (const float*)d_in[16];
    const float* Wlog   = (const float*)d_in[17];
    const float* blog   = (const float*)d_in[18];
    float* out = (float*)d_out;

    float *x, *h, *q, *k, *v, *att, *proj, *up;
    uint32_t* wtf;
    cudaGetSymbolAddress((void**)&x,    g_x);
    cudaGetSymbolAddress((void**)&h,    g_h);
    cudaGetSymbolAddress((void**)&q,    g_q);
    cudaGetSymbolAddress((void**)&k,    g_k);
    cudaGetSymbolAddress((void**)&v,    g_v);
    cudaGetSymbolAddress((void**)&att,  g_att);
    cudaGetSymbolAddress((void**)&proj, g_proj);
    cudaGetSymbolAddress((void**)&up,   g_up);
    cudaGetSymbolAddress((void**)&wtf,  g_wtf);

    cudaFuncSetAttribute(gemm_tf32_kernel,
                         cudaFuncAttributeMaxDynamicSharedMemorySize, kGemmSmem);
    cudaFuncSetAttribute(flash_attn_mma,
                         cudaFuncAttributeMaxDynamicSharedMemorySize, kAttnSmem);

    // per-launch weight convert + transpose ([K][N] -> [N][K] tf32 bits)
    for (int i = 0; i < kNL; ++i) {
        launch_cvt_t(Wq    + (size_t)i * kD * kD,  wtf + kWq  + (size_t)i * kD * kD,  kD,  kD);
        launch_cvt_t(Wk    + (size_t)i * kD * kD,  wtf + kWk  + (size_t)i * kD * kD,  kD,  kD);
        launch_cvt_t(Wv    + (size_t)i * kD * kD,  wtf + kWv  + (size_t)i * kD * kD,  kD,  kD);
        launch_cvt_t(Wo    + (size_t)i * kD * kD,  wtf + kWo  + (size_t)i * kD * kD,  kD,  kD);
        launch_cvt_t(Wproj + (size_t)i * kD * kD2, wtf + kWpj + (size_t)i * kD * kD2, kD,  kD2);
        launch_cvt_t(Wup   + (size_t)i * kD * kD2, wtf + kWup + (size_t)i * kD * kD2, kD,  kD2);
        launch_cvt_t(Wdown + (size_t)i * kD2 * kD, wtf + kWdn + (size_t)i * kD2 * kD, kD2, kD);
    }
    launch_cvt_t(Wlog, wtf + kWlg, kD, kV);

    embed_pe_kernel<<<kBL, 256>>>(ids, embed, x);

    for (int i = 0; i < kNL; ++i) {
        rmsnorm_kernel<<<kBL, 256>>>(x, gammas + (size_t)(2 * i) * kD, h);
        launch_gemm(h, wtf + kWq + (size_t)i * kD * kD, bq + (size_t)i * kD, nullptr, q, kBL, kD, kD);
        launch_gemm(h, wtf + kWk + (size_t)i * kD * kD, bk + (size_t)i * kD, nullptr, k, kBL, kD, kD);
        launch_gemm(h, wtf + kWv + (size_t)i * kD * kD, bv + (size_t)i * kD, nullptr, v, kBL, kD, kD);
        flash_attn_mma<<<dim3(kL / 64, kB * kH), 128, kAttnSmem>>>(q, k, v, att);
        launch_gemm(att, wtf + kWo + (size_t)i * kD * kD, bo + (size_t)i * kD, x, x, kBL, kD, kD);
        rmsnorm_kernel<<<kBL, 256>>>(x, gammas + (size_t)(2 * i + 1) * kD, h);
        launch_gemm(h, wtf + kWpj + (size_t)i * kD * kD2, bproj + (size_t)i * kD2, nullptr, proj, kBL, kD2, kD);
        launch_gemm(h, wtf + kWup + (size_t)i * kD * kD2, bup + (size_t)i * kD2, nullptr, up, kBL, kD2, kD);
        silu_gate_kernel<<<((size_t)kBL * kD2) / (256 * 4), 256>>>(proj, up);
        launch_gemm(proj, wtf + kWdn + (size_t)i * kD2 * kD, bdown + (size_t)i * kD, x, x, kBL, kD, kD2);
    }
    // round x once for the logits GEMM A operand (reuse g_h as bit buffer)
    int n4 = (kBL * kD) / 4;
    cvt_tf32_kernel<<<(n4 + 255) / 256, 256>>>(x, (uint32_t*)h, n4);
    launch_gemm(h, wtf + kWlg, blog, nullptr, out, kBL, kV, kD);
}

// round 8
// speedup vs baseline: 2.2468x; 1.2969x over previous
#include <cuda_runtime.h>
#include <cuda_fp16.h>
#include <math.h>
#include <stdint.h>

// ---------------- problem constants ----------------
constexpr int kNL = 4;
constexpr int kD  = 1024;
constexpr int kD2 = 2048;
constexpr int kH  = 16;
constexpr int kDH = 64;
constexpr int kV  = 32000;
constexpr int kB  = 2;
constexpr int kL  = 2048;
constexpr int kBL = kB * kL;   // 4096
#define EPSF 1e-6f

// ---------------- scratch (device globals; no allocation allowed) ----------------
__device__ __align__(1024) float g_x[kBL * kD];        // residual stream (fp32)
__device__ __align__(1024) float g_q[kBL * kD];
__device__ __align__(1024) float g_k[kBL * kD];
__device__ __align__(1024) float g_v[kBL * kD];
__device__ __align__(1024) float g_proj[(size_t)kBL * kD2];
__device__ __align__(1024) float g_up[(size_t)kBL * kD2];
__device__ __align__(1024) __half g_h[kBL * kD];       // rmsnorm out / logits A (fp16)
__device__ __align__(1024) __half g_att[kBL * kD];     // attention out (fp16)
__device__ __align__(1024) __half g_gate[(size_t)kBL * kD2];  // silu out (fp16)

// fp16-converted + TRANSPOSED weights, layout [N][K] per matrix.
constexpr size_t kWq   = 0;
constexpr size_t kWk   = kWq   + (size_t)kNL * kD * kD;
constexpr size_t kWv   = kWk   + (size_t)kNL * kD * kD;
constexpr size_t kWo   = kWv   + (size_t)kNL * kD * kD;
constexpr size_t kWpj  = kWo   + (size_t)kNL * kD * kD2;
constexpr size_t kWup  = kWpj  + (size_t)kNL * kD * kD2;
constexpr size_t kWdn  = kWup  + (size_t)kNL * kD * kD2;
constexpr size_t kWlg  = kWdn  + (size_t)kNL * kD2 * kD;
constexpr size_t kWTot = kWlg  + (size_t)kD * kV;
__device__ __align__(1024) __half g_wh[kWTot];

// ---------------- small helpers ----------------
__device__ __forceinline__ uint32_t f2tf32(float f) {
    uint32_t u;
    asm("cvt.rna.tf32.f32 %0, %1;" : "=r"(u) : "f"(f));
    return u;
}
__device__ __forceinline__ void mma_tf32(float* c, const uint32_t* a, uint32_t b0, uint32_t b1) {
    asm volatile(
        "mma.sync.aligned.m16n8k8.row.col.f32.tf32.tf32.f32 "
        "{%0,%1,%2,%3}, {%4,%5,%6,%7}, {%8,%9}, {%0,%1,%2,%3};"
        : "+f"(c[0]), "+f"(c[1]), "+f"(c[2]), "+f"(c[3])
        : "r"(a[0]), "r"(a[1]), "r"(a[2]), "r"(a[3]), "r"(b0), "r"(b1));
}
__device__ __forceinline__ void mma_f16(float* c, const uint32_t* a, uint32_t b0, uint32_t b1) {
    asm volatile(
        "mma.sync.aligned.m16n8k16.row.col.f32.f16.f16.f32 "
        "{%0,%1,%2,%3}, {%4,%5,%6,%7}, {%8,%9}, {%0,%1,%2,%3};"
        : "+f"(c[0]), "+f"(c[1]), "+f"(c[2]), "+f"(c[3])
        : "r"(a[0]), "r"(a[1]), "r"(a[2]), "r"(a[3]), "r"(b0), "r"(b1));
}
__device__ __forceinline__ void cp16(uint32_t dst, const void* src) {
    asm volatile("cp.async.cg.shared.global [%0], [%1], 16;" :: "r"(dst), "l"(src));
}
__device__ __forceinline__ void ldsm4(uint32_t& r0, uint32_t& r1, uint32_t& r2, uint32_t& r3,
                                      uint32_t addr) {
    asm volatile("ldmatrix.sync.aligned.m8n8.x4.shared.b16 {%0,%1,%2,%3}, [%4];"
                 : "=r"(r0), "=r"(r1), "=r"(r2), "=r"(r3) : "r"(addr));
}

// ---------------- fp16 convert + transpose: in[K][N] fp32 -> out[N][K] fp16 ------------
__global__ void cvt_t_kernel(const float* __restrict__ in, __half* __restrict__ out,
                             int K, int N)
{
    __shared__ __half tile[32][33];
    int kb = blockIdx.y * 32, nb = blockIdx.x * 32;
    int tx = threadIdx.x & 31, ty = threadIdx.x >> 5;
#pragma unroll
    for (int r = ty; r < 32; r += 8)
        tile[r][tx] = __float2half_rn(in[(size_t)(kb + r) * N + nb + tx]);
    __syncthreads();
#pragma unroll
    for (int r = ty; r < 32; r += 8)
        out[(size_t)(nb + r) * K + kb + tx] = tile[tx][r];
}

// ---------------- fp32 -> fp16 convert (logits activations) ----------------
__global__ void cvt_h_kernel(const float* __restrict__ in,
                             __half* __restrict__ out, int n4)
{
    int i = blockIdx.x * blockDim.x + threadIdx.x;
    if (i >= n4) return;
    float4 v = ((const float4*)in)[i];
    __half2* op = (__half2*)(out + (size_t)i * 4);
    op[0] = __floats2half2_rn(v.x, v.y);
    op[1] = __floats2half2_rn(v.z, v.w);
}

// ---------------- embed + positional encoding ----------------
__global__ void embed_pe_kernel(const int* __restrict__ ids,
                                const float* __restrict__ embed,
                                float* __restrict__ x)
{
    int row = blockIdx.x;
    int l   = row % kL;
    int id  = ids[row];
    int d0  = threadIdx.x * 4;
    float4 ev = *(const float4*)&embed[(size_t)id * kD + d0];
    float out[4] = {ev.x, ev.y, ev.z, ev.w};
    const float negc = -0.0089944731f;   // -log(10000)/1024 in fp32
#pragma unroll
    for (int t = 0; t < 4; ++t) {
        int d  = d0 + t;
        int i2 = (d >> 1) * 2;
        float freq = expf((float)i2 * negc);
        float a    = (float)l * freq;
        out[t] += (d & 1) ? cosf(a) : sinf(a);
    }
    *(float4*)&x[(size_t)row * kD + d0] = make_float4(out[0], out[1], out[2], out[3]);
}

// ---------------- rmsnorm (emits fp16) ----------------
__global__ void rmsnorm_kernel(const float* __restrict__ x,
                               const float* __restrict__ gamma,
                               __half* __restrict__ y)
{
    int row = blockIdx.x;
    const float* xr = x + (size_t)row * kD;
    int d0 = threadIdx.x * 4;
    float4 v = *(const float4*)&xr[d0];
    float ss = v.x * v.x + v.y * v.y + v.z * v.z + v.w * v.w;
#pragma unroll
    for (int off = 16; off; off >>= 1)
        ss += __shfl_xor_sync(0xffffffffu, ss, off);
    __shared__ float ws[8];
    int lane = threadIdx.x & 31, w = threadIdx.x >> 5;
    if (lane == 0) ws[w] = ss;
    __syncthreads();
    if (w == 0) {
        float t = (lane < 8) ? ws[lane] : 0.0f;
#pragma unroll
        for (int off = 4; off; off >>= 1)
            t += __shfl_xor_sync(0xffffffffu, t, off);
        if (lane == 0) ws[0] = t;
    }
    __syncthreads();
    float scale = rsqrtf(ws[0] / (float)kD + EPSF);
    float4 g = *(const float4*)&gamma[d0];
    __half2* yp = (__half2*)&y[(size_t)row * kD + d0];
    yp[0] = __floats2half2_rn(v.x * scale * g.x, v.y * scale * g.y);
    yp[1] = __floats2half2_rn(v.z * scale * g.z, v.w * scale * g.w);
}

// ---------------- silu gate: gate = fp16(silu(proj * up)) ----------------
__global__ void silu_gate_kernel(const float* __restrict__ proj,
                                 const float* __restrict__ up,
                                 __half* __restrict__ gate)
{
    size_t i = ((size_t)blockIdx.x * blockDim.x + threadIdx.x) * 4;
    float4 p = *(const float4*)&proj[i];
    float4 u = *(const float4*)&up[i];
    float t0 = p.x * u.x, t1 = p.y * u.y, t2 = p.z * u.z, t3 = p.w * u.w;
    float s0 = t0 / (1.0f + __expf(-t0));
    float s1 = t1 / (1.0f + __expf(-t1));
    float s2 = t2 / (1.0f + __expf(-t2));
    float s3 = t3 / (1.0f + __expf(-t3));
    __half2* gp = (__half2*)&gate[i];
    gp[0] = __floats2half2_rn(s0, s1);
    gp[1] = __floats2half2_rn(s2, s3);
}

// ================= FP16 tensor-core GEMM =================
// C[M,N] = A[M,K] @ Bt[N,K]^T + bias (+resid). A,Bt fp16; C fp32.
// 128x128x32 block tile, 8 warps (2x4), 64x32 warp tile, m16n8k16.f16.f32.
// Smem tiles [128 rows][32 halves], pitch 40 halves (80B) -> conflict-free LDSM.
// cp.async double buffer (R5-proven pipeline).

constexpr int kABytes = 128 * 40 * 2;      // 10240 bytes per operand tile
constexpr int kBufBytes = 2 * kABytes;     // 20480 per buffer (A+B)
constexpr int kGemmSmem = 2 * kBufBytes;   // 40960

__global__ void __launch_bounds__(256, 2)
gemm_f16_kernel(const __half* __restrict__ A, const __half* __restrict__ Bt,
                const float* __restrict__ bias, const float* __restrict__ resid,
                float* __restrict__ C, int M, int N, int K)
{
    extern __shared__ char smem[];
    uint32_t base = (uint32_t)__cvta_generic_to_shared(smem);

    int tid  = threadIdx.x;
    int lane = tid & 31;
    int warp = tid >> 5;
    int wm = warp >> 2;                    // 0..1
    int wn = warp & 3;                     // 0..3
    int bm = blockIdx.y, bn = blockIdx.x;

    const __half* Ab = A  + (size_t)bm * 128 * K;
    const __half* Bb = Bt + (size_t)(bn * 128) * K;

    // cp.async decomposition: 2 chunks of 16B per operand per thread
    int rw[2], sub[2];
    uint32_t dstA[2], dstB[2];
#pragma unroll
    for (int i = 0; i < 2; ++i) {
        int c = i * 256 + tid;
        rw[i]  = c >> 2;          // row 0..127
        sub[i] = c & 3;           // 16B chunk within 64B row
        dstA[i] = base + (uint32_t)(rw[i] * 80 + sub[i] * 16);
        dstB[i] = base + (uint32_t)(kABytes + rw[i] * 80 + sub[i] * 16);
    }

    // ldmatrix base addresses
    int q  = lane >> 3;          // 0..3
    int r8 = lane & 7;
    uint32_t aAddr = base + (uint32_t)((wm * 64 + (q & 1) * 8 + r8) * 80 + (q >> 1) * 16);
    uint32_t bAddr = base + (uint32_t)(kABytes + (wn * 32 + (q & 1) * 8 + r8) * 80 + (q >> 1) * 16);

    float acc[4][4][4];
#pragma unroll
    for (int mt = 0; mt < 4; ++mt)
#pragma unroll
        for (int nt = 0; nt < 4; ++nt)
#pragma unroll
            for (int r = 0; r < 4; ++r) acc[mt][nt][r] = 0.0f;

    int nit = K >> 5;   // K-chunks of 32 halves

#pragma unroll
    for (int i = 0; i < 2; ++i) {
        cp16(dstA[i], &Ab[(size_t)rw[i] * K + sub[i] * 8]);
        cp16(dstB[i], &Bb[(size_t)rw[i] * K + sub[i] * 8]);
    }
    asm volatile("cp.async.commit_group;");

    for (int it = 0; it < nit; ++it) {
        int buf = it & 1;
        uint32_t bufoff = buf ? (uint32_t)kBufBytes : 0u;
        if (it + 1 < nit) {
            int k0 = (it + 1) << 5;
            uint32_t noff = (buf ^ 1) ? (uint32_t)kBufBytes : 0u;
#pragma unroll
            for (int i = 0; i < 2; ++i) {
                cp16(dstA[i] + noff, &Ab[(size_t)rw[i] * K + k0 + sub[i] * 8]);
                cp16(dstB[i] + noff, &Bb[(size_t)rw[i] * K + k0 + sub[i] * 8]);
            }
            asm volatile("cp.async.commit_group;");
            asm volatile("cp.async.wait_group 1;");
        } else {
            asm volatile("cp.async.wait_group 0;");
        }
        __syncthreads();

#pragma unroll
        for (int ks = 0; ks < 2; ++ks) {     // two k16 steps per chunk
            uint32_t koff = bufoff + (uint32_t)(ks * 32);   // 16 halves = 32B
            uint32_t afr[4][4], bfr[4][2];
#pragma unroll
            for (int mt = 0; mt < 4; ++mt)
                ldsm4(afr[mt][0], afr[mt][1], afr[mt][2], afr[mt][3],
                      aAddr + koff + (uint32_t)(mt * 16 * 80));
#pragma unroll
            for (int ntp = 0; ntp < 2; ++ntp) {
                uint32_t r0, r1, r2, r3;
                ldsm4(r0, r1, r2, r3, bAddr + koff + (uint32_t)(ntp * 16 * 80));
                bfr[2 * ntp][0] = r0; bfr[2 * ntp + 1][0] = r1;
                bfr[2 * ntp][1] = r2; bfr[2 * ntp + 1][1] = r3;
            }
#pragma unroll
            for (int mt = 0; mt < 4; ++mt)
#pragma unroll
                for (int nt = 0; nt < 4; ++nt)
                    mma_f16(acc[mt][nt], afr[mt], bfr[nt][0], bfr[nt][1]);
        }
        __syncthreads();
    }

    // epilogue: bias (+resid) and store
    int rb = bm * 128 + wm * 64 + (lane >> 2);
    int cb = bn * 128 + wn * 32 + (lane & 3) * 2;
#pragma unroll
    for (int mt = 0; mt < 4; ++mt) {
#pragma unroll
        for (int nt = 0; nt < 4; ++nt) {
            int r0 = rb + mt * 16;
            int c0 = cb + nt * 8;
            float b0 = bias[c0], b1 = bias[c0 + 1];
            size_t off0 = (size_t)r0 * N + c0;
            size_t off1 = (size_t)(r0 + 8) * N + c0;
            float v0 = acc[mt][nt][0] + b0, v1 = acc[mt][nt][1] + b1;
            float v2 = acc[mt][nt][2] + b0, v3 = acc[mt][nt][3] + b1;
            if (resid) {
                float2 rr0 = *(const float2*)&resid[off0];
                float2 rr1 = *(const float2*)&resid[off1];
                v0 += rr0.x; v1 += rr0.y; v2 += rr1.x; v3 += rr1.y;
            }
            *(float2*)&C[off0] = make_float2(v0, v1);
            *(float2*)&C[off1] = make_float2(v2, v3);
        }
    }
}

// ================= flash attention with TF32 MMA (R5, fp16 output) =================
constexpr int kKV = 68;
constexpr int kAttnSmem = (64 * kKV * 2 + 4 * 16 * kKV) * 4;  // 52224 bytes

__global__ void __launch_bounds__(128)
flash_attn_mma(const float* __restrict__ Q, const float* __restrict__ K,
               const float* __restrict__ Vv, __half* __restrict__ O)
{
    extern __shared__ uint32_t asmem[];
    uint32_t* Ks = asmem;
    uint32_t* Vs = asmem + 64 * kKV;
    float*    Ps = (float*)(asmem + 2 * 64 * kKV) + (threadIdx.x >> 5) * 16 * kKV;

    int tid = threadIdx.x, lane = tid & 31, w = tid >> 5;
    int g = lane >> 2, tg = lane & 3;
    int bh = blockIdx.y;
    int b  = bh >> 4;
    int h  = bh & 15;
    int q0 = blockIdx.x * 64;
    size_t base = ((size_t)b * kL) * kD + (size_t)h * kDH;
    int rlo = q0 + w * 16 + g;

    uint32_t qf[8][4];
    {
        const float* Qp = Q + base + (size_t)rlo * kD;
#pragma unroll
        for (int ks = 0; ks < 8; ++ks) {
            int kk = ks * 8 + tg;
            qf[ks][0] = f2tf32(Qp[kk]);
            qf[ks][1] = f2tf32(Qp[(size_t)8 * kD + kk]);
            qf[ks][2] = f2tf32(Qp[kk + 4]);
            qf[ks][3] = f2tf32(Qp[(size_t)8 * kD + kk + 4]);
        }
    }

    float of[8][4];
#pragma unroll
    for (int nt = 0; nt < 8; ++nt)
#pragma unroll
        for (int e = 0; e < 4; ++e) of[nt][e] = 0.0f;
    float mlo = -1e30f, mhi = -1e30f, llo = 0.0f, lhi = 0.0f;

    int nkt = blockIdx.x + 1;
    for (int kt = 0; kt < nkt; ++kt) {
        int k0 = kt * 64;
        __syncthreads();
#pragma unroll
        for (int i = 0; i < 8; ++i) {
            int c = i * 128 + tid;
            int row = c >> 4, f4 = (c & 15) * 4;
            float4 kv = *(const float4*)&K[base + (size_t)(k0 + row) * kD + f4];
            *(uint4*)&Ks[row * kKV + f4] =
                make_uint4(f2tf32(kv.x), f2tf32(kv.y), f2tf32(kv.z), f2tf32(kv.w));
            float4 vv = *(const float4*)&Vv[base + (size_t)(k0 + row) * kD + f4];
            *(uint4*)&Vs[row * kKV + f4] =
                make_uint4(f2tf32(vv.x), f2tf32(vv.y), f2tf32(vv.z), f2tf32(vv.w));
        }
        __syncthreads();

        float s[8][4];
#pragma unroll
        for (int nt = 0; nt < 8; ++nt)
#pragma unroll
            for (int e = 0; e < 4; ++e) s[nt][e] = 0.0f;
#pragma unroll
        for (int ks = 0; ks < 8; ++ks) {
            int kk = ks * 8 + tg;
#pragma unroll
            for (int nt = 0; nt < 8; ++nt) {
                int n0 = nt * 8 + g;
                mma_tf32(s[nt], qf[ks], Ks[n0 * kKV + kk], Ks[n0 * kKV + kk + 4]);
            }
        }

        bool diag = (kt == blockIdx.x);
        float rmlo = -1e30f, rmhi = -1e30f;
#pragma unroll
        for (int nt = 0; nt < 8; ++nt) {
#pragma unroll
            for (int e = 0; e < 4; ++e) {
                float v = s[nt][e] * 0.125f;
                if (diag) {
                    int key = k0 + nt * 8 + 2 * tg + (e & 1);
                    int row = (e < 2) ? rlo : rlo + 8;
                    if (key > row) v = -1e30f;
                }
                s[nt][e] = v;
                if (e < 2) rmlo = fmaxf(rmlo, v); else rmhi = fmaxf(rmhi, v);
            }
        }
        rmlo = fmaxf(rmlo, __shfl_xor_sync(0xffffffffu, rmlo, 1));
        rmlo = fmaxf(rmlo, __shfl_xor_sync(0xffffffffu, rmlo, 2));
        rmhi = fmaxf(rmhi, __shfl_xor_sync(0xffffffffu, rmhi, 1));
        rmhi = fmaxf(rmhi, __shfl_xor_sync(0xffffffffu, rmhi, 2));
        float mnlo = fmaxf(mlo, rmlo), mnhi = fmaxf(mhi, rmhi);
        float clo = __expf(mlo - mnlo), chi = __expf(mhi - mnhi);
        mlo = mnlo; mhi = mnhi;

        float rslo = 0.0f, rshi = 0.0f;
#pragma unroll
        for (int nt = 0; nt < 8; ++nt) {
            float p0 = __expf(s[nt][0] - mlo);
            float p1 = __expf(s[nt][1] - mlo);
            float p2 = __expf(s[nt][2] - mhi);
            float p3 = __expf(s[nt][3] - mhi);
            rslo += p0 + p1; rshi += p2 + p3;
            int col = nt * 8 + 2 * tg;
            *(float2*)&Ps[g * kKV + col]       = make_float2(p0, p1);
            *(float2*)&Ps[(g + 8) * kKV + col] = make_float2(p2, p3);
        }
        rslo += __shfl_xor_sync(0xffffffffu, rslo, 1);
        rslo += __shfl_xor_sync(0xffffffffu, rslo, 2);
        rshi += __shfl_xor_sync(0xffffffffu, rshi, 1);
        rshi += __shfl_xor_sync(0xffffffffu, rshi, 2);
        llo = llo * clo + rslo;
        lhi = lhi * chi + rshi;
#pragma unroll
        for (int nt = 0; nt < 8; ++nt) {
            of[nt][0] *= clo; of[nt][1] *= clo;
            of[nt][2] *= chi; of[nt][3] *= chi;
        }
        __syncwarp();

#pragma unroll
        for (int ks = 0; ks < 8; ++ks) {
            int kk = ks * 8 + tg;
            uint32_t pa[4];
            pa[0] = f2tf32(Ps[g * kKV + kk]);
            pa[1] = f2tf32(Ps[(g + 8) * kKV + kk]);
            pa[2] = f2tf32(Ps[g * kKV + kk + 4]);
            pa[3] = f2tf32(Ps[(g + 8) * kKV + kk + 4]);
#pragma unroll
            for (int nt = 0; nt < 8; ++nt) {
                int n0 = nt * 8 + g;
                mma_tf32(of[nt], pa, Vs[kk * kKV + n0], Vs[(kk + 4) * kKV + n0]);
            }
        }
    }

    // epilogue: normalize, emit fp16 (feeds Wo GEMM A operand)
    float ilo = 1.0f / llo, ihi = 1.0f / lhi;
#pragma unroll
    for (int nt = 0; nt < 8; ++nt) {
        int col = nt * 8 + 2 * tg;
        size_t off0 = base + (size_t)rlo * kD + col;
        size_t off1 = base + (size_t)(rlo + 8) * kD + col;
        *(__half2*)&O[off0] = __floats2half2_rn(of[nt][0] * ilo, of[nt][1] * ilo);
        *(__half2*)&O[off1] = __floats2half2_rn(of[nt][2] * ihi, of[nt][3] * ihi);
    }
}

// ---------------- host launcher ----------------
static void launch_gemm(const __half* A, const __half* Bt, const float* bias,
                        const float* resid, float* C, int M, int N, int K)
{
    dim3 grid(N / 128, M / 128);
    gemm_f16_kernel<<<grid, 256, kGemmSmem>>>(A, Bt, bias, resid, C, M, N, K);
}
static void launch_cvt_t(const float* in, __half* out, int K, int N)
{
    dim3 grid(N / 32, K / 32);
    cvt_t_kernel<<<grid, 256>>>(in, out, K, N);
}

extern "C" void kernel_launch(void* const* d_in, const int* in_sizes, int n_in,
                              void* d_out, int out_size)
{
    const int*   ids    = (const int*)  d_in[0];
    const float* embed  = (const float*)d_in[1];
    const float* Wq     = (const float*)d_in[2];
    const float* bq     = (const float*)d_in[3];
    const float* Wk     = (const float*)d_in[4];
    const float* bk     = (const float*)d_in[5];
    const float* Wv     = (const float*)d_in[6];
    const float* bv     = (const float*)d_in[7];
    const float* Wo     = (const float*)d_in[8];
    const float* bo     = (const float*)d_in[9];
    const float* Wproj  = (const float*)d_in[10];
    const float* bproj  = (const float*)d_in[11];
    const float* Wup    = (const float*)d_in[12];
    const float* bup    = (const float*)d_in[13];
    const float* Wdown  = (const float*)d_in[14];
    const float* bdown  = (const float*)d_in[15];
    const float* gammas = (const float*)d_in[16];
    const float* Wlog   = (const float*)d_in[17];
    const float* blog   = (const float*)d_in[18];
    float* out = (float*)d_out;

    float *x, *q, *k, *v, *proj, *up;
    __half *h, *att, *gate, *wh;
    cudaGetSymbolAddress((void**)&x,    g_x);
    cudaGetSymbolAddress((void**)&q,    g_q);
    cudaGetSymbolAddress((void**)&k,    g_k);
    cudaGetSymbolAddress((void**)&v,    g_v);
    cudaGetSymbolAddress((void**)&proj, g_proj);
    cudaGetSymbolAddress((void**)&up,   g_up);
    cudaGetSymbolAddress((void**)&h,    g_h);
    cudaGetSymbolAddress((void**)&att,  g_att);
    cudaGetSymbolAddress((void**)&gate, g_gate);
    cudaGetSymbolAddress((void**)&wh,   g_wh);

    cudaFuncSetAttribute(flash_attn_mma,
                         cudaFuncAttributeMaxDynamicSharedMemorySize, kAttnSmem);

    // per-launch weight convert + transpose ([K][N] fp32 -> [N][K] fp16)
    for (int i = 0; i < kNL; ++i) {
        launch_cvt_t(Wq    + (size_t)i * kD * kD,  wh + kWq  + (size_t)i * kD * kD,  kD,  kD);
        launch_cvt_t(Wk    + (size_t)i * kD * kD,  wh + kWk  + (size_t)i * kD * kD,  kD,  kD);
        launch_cvt_t(Wv    + (size_t)i * kD * kD,  wh + kWv  + (size_t)i * kD * kD,  kD,  kD);
        launch_cvt_t(Wo    + (size_t)i * kD * kD,  wh + kWo  + (size_t)i * kD * kD,  kD,  kD);
        launch_cvt_t(Wproj + (size_t)i * kD * kD2, wh + kWpj + (size_t)i * kD * kD2, kD,  kD2);
        launch_cvt_t(Wup   + (size_t)i * kD * kD2, wh + kWup + (size_t)i * kD * kD2, kD,  kD2);
        launch_cvt_t(Wdown + (size_t)i * kD2 * kD, wh + kWdn + (size_t)i * kD2 * kD, kD2, kD);
    }
    launch_cvt_t(Wlog, wh + kWlg, kD, kV);

    embed_pe_kernel<<<kBL, 256>>>(ids, embed, x);

    for (int i = 0; i < kNL; ++i) {
        rmsnorm_kernel<<<kBL, 256>>>(x, gammas + (size_t)(2 * i) * kD, h);
        launch_gemm(h, wh + kWq + (size_t)i * kD * kD, bq + (size_t)i * kD, nullptr, q, kBL, kD, kD);
        launch_gemm(h, wh + kWk + (size_t)i * kD * kD, bk + (size_t)i * kD, nullptr, k, kBL, kD, kD);
        launch_gemm(h, wh + kWv + (size_t)i * kD * kD, bv + (size_t)i * kD, nullptr, v, kBL, kD, kD);
        flash_attn_mma<<<dim3(kL / 64, kB * kH), 128, kAttnSmem>>>(q, k, v, att);
        launch_gemm(att, wh + kWo + (size_t)i * kD * kD, bo + (size_t)i * kD, x, x, kBL, kD, kD);
        rmsnorm_kernel<<<kBL, 256>>>(x, gammas + (size_t)(2 * i + 1) * kD, h);
        launch_gemm(h, wh + kWpj + (size_t)i * kD * kD2, bproj + (size_t)i * kD2, nullptr, proj, kBL, kD2, kD);
        launch_gemm(h, wh + kWup + (size_t)i * kD * kD2, bup + (size_t)i * kD2, nullptr, up, kBL, kD2, kD);
        silu_gate_kernel<<<((size_t)kBL * kD2) / (256 * 4), 256>>>(proj, up, gate);
        launch_gemm(gate, wh + kWdn + (size_t)i * kD2 * kD, bdown + (size_t)i * kD, x, x, kBL, kD, kD2);
    }
    // convert x once for the logits GEMM A operand
    int n4 = (kBL * kD) / 4;
    cvt_h_kernel<<<(n4 + 255) / 256, 256>>>(x, h, n4);
    launch_gemm(h, wh + kWlg, blog, nullptr, out, kBL, kV, kD);
}

// round 9
// speedup vs baseline: 2.3691x; 1.0544x over previous
#include <cuda_runtime.h>
#include <cuda_fp16.h>
#include <math.h>
#include <stdint.h>

// ---------------- problem constants ----------------
constexpr int kNL = 4;
constexpr int kD  = 1024;
constexpr int kD2 = 2048;
constexpr int kH  = 16;
constexpr int kDH = 64;
constexpr int kV  = 32000;
constexpr int kB  = 2;
constexpr int kL  = 2048;
constexpr int kBL = kB * kL;   // 4096
constexpr int kQS = 3 * kD;    // fused qkv row stride (3072)
constexpr int kPU = 2 * kD2;   // fused proj/up row stride (4096)
#define EPSF 1e-6f

// ---------------- scratch (device globals; no allocation allowed) ----------------
__device__ __align__(1024) float g_x[kBL * kD];                 // residual (fp32)
__device__ __align__(1024) float g_qkv[(size_t)kBL * kQS];      // fused q|k|v (fp32)
__device__ __align__(1024) float g_pu[(size_t)kBL * kPU];       // fused proj|up (fp32)
__device__ __align__(1024) __half g_h[kBL * kD];                // rmsnorm out / logits A
__device__ __align__(1024) __half g_att[kBL * kD];              // attention out
__device__ __align__(1024) __half g_gate[(size_t)kBL * kD2];    // silu out
__device__ __align__(1024) float g_bqkv[kNL * kQS];             // fused qkv bias
__device__ __align__(1024) float g_bpu[kNL * kPU];              // fused proj/up bias

// fp16 + TRANSPOSED weights, [N][K] blocks. Per-layer fused layouts.
constexpr size_t kDD = (size_t)kD * kD;                 // 1M
__device__ __forceinline__ __host__ size_t qkvOff(int i) { return (size_t)i * 3 * kDD; }
constexpr size_t kWoBase = (size_t)kNL * 3 * kDD;       // 12M
__device__ __forceinline__ __host__ size_t woOff(int i)  { return kWoBase + (size_t)i * kDD; }
constexpr size_t kPuBase = kWoBase + (size_t)kNL * kDD; // 16M
__device__ __forceinline__ __host__ size_t puOff(int i)  { return kPuBase + (size_t)i * 4 * kDD; }
constexpr size_t kDnBase = kPuBase + (size_t)kNL * 4 * kDD; // 32M
__device__ __forceinline__ __host__ size_t dnOff(int i)  { return kDnBase + (size_t)i * 2 * kDD; }
constexpr size_t kLgBase = kDnBase + (size_t)kNL * 2 * kDD; // 40M
constexpr size_t kWTot = kLgBase + (size_t)kD * kV;         // 72.768M
__device__ __align__(1024) __half g_wh[kWTot];

// ---------------- small helpers ----------------
__device__ __forceinline__ uint32_t f2tf32(float f) {
    uint32_t u;
    asm("cvt.rna.tf32.f32 %0, %1;" : "=r"(u) : "f"(f));
    return u;
}
__device__ __forceinline__ void mma_tf32(float* c, const uint32_t* a, uint32_t b0, uint32_t b1) {
    asm volatile(
        "mma.sync.aligned.m16n8k8.row.col.f32.tf32.tf32.f32 "
        "{%0,%1,%2,%3}, {%4,%5,%6,%7}, {%8,%9}, {%0,%1,%2,%3};"
        : "+f"(c[0]), "+f"(c[1]), "+f"(c[2]), "+f"(c[3])
        : "r"(a[0]), "r"(a[1]), "r"(a[2]), "r"(a[3]), "r"(b0), "r"(b1));
}
__device__ __forceinline__ void mma_f16(float* c, const uint32_t* a, uint32_t b0, uint32_t b1) {
    asm volatile(
        "mma.sync.aligned.m16n8k16.row.col.f32.f16.f16.f32 "
        "{%0,%1,%2,%3}, {%4,%5,%6,%7}, {%8,%9}, {%0,%1,%2,%3};"
        : "+f"(c[0]), "+f"(c[1]), "+f"(c[2]), "+f"(c[3])
        : "r"(a[0]), "r"(a[1]), "r"(a[2]), "r"(a[3]), "r"(b0), "r"(b1));
}
__device__ __forceinline__ void cp16(uint32_t dst, const void* src) {
    asm volatile("cp.async.cg.shared.global [%0], [%1], 16;" :: "r"(dst), "l"(src));
}
__device__ __forceinline__ void ldsm4(uint32_t& r0, uint32_t& r1, uint32_t& r2, uint32_t& r3,
                                      uint32_t addr) {
    asm volatile("ldmatrix.sync.aligned.m8n8.x4.shared.b16 {%0,%1,%2,%3}, [%4];"
                 : "=r"(r0), "=r"(r1), "=r"(r2), "=r"(r3) : "r"(addr));
}

// ---------------- fp16 convert + transpose: in[K][N] fp32 -> out[N][K] fp16 ------------
// 64(K) x 32(N) tiles: transposed writes are 128B per n-row, 16B per thread.
__global__ void cvt_t_kernel(const float* __restrict__ in, __half* __restrict__ out,
                             int K, int N)
{
    __shared__ __half tile[64][33];
    int kb = blockIdx.y * 64, nb = blockIdx.x * 32;
    int tx = threadIdx.x & 31, ty = threadIdx.x >> 5;
#pragma unroll
    for (int r = ty; r < 64; r += 8)
        tile[r][tx] = __float2half_rn(in[(size_t)(kb + r) * N + nb + tx]);
    __syncthreads();
    int n  = threadIdx.x >> 3;          // 0..31
    int k0 = (threadIdx.x & 7) * 8;     // 0..56, halves
    __half2 hv[4];
#pragma unroll
    for (int j = 0; j < 4; ++j)
        hv[j] = __halves2half2(tile[k0 + 2 * j][n], tile[k0 + 2 * j + 1][n]);
    *(uint4*)&out[(size_t)(nb + n) * K + kb + k0] = *(uint4*)hv;
}

// ---------------- fp32 -> fp16 convert (logits activations) ----------------
__global__ void cvt_h_kernel(const float* __restrict__ in,
                             __half* __restrict__ out, int n4)
{
    int i = blockIdx.x * blockDim.x + threadIdx.x;
    if (i >= n4) return;
    float4 v = ((const float4*)in)[i];
    __half2* op = (__half2*)(out + (size_t)i * 4);
    op[0] = __floats2half2_rn(v.x, v.y);
    op[1] = __floats2half2_rn(v.z, v.w);
}

// ---------------- bias concat kernels ----------------
__global__ void catbias3_kernel(const float* __restrict__ a, const float* __restrict__ b,
                                const float* __restrict__ c, float* __restrict__ o)
{
    int l = blockIdx.y;
    int i = blockIdx.x * 256 + threadIdx.x;   // 0..3*kD-1
    float v;
    if (i < kD)           v = a[l * kD + i];
    else if (i < 2 * kD)  v = b[l * kD + i - kD];
    else                  v = c[l * kD + i - 2 * kD];
    o[(size_t)l * kQS + i] = v;
}
__global__ void catbias2_kernel(const float* __restrict__ a, const float* __restrict__ b,
                                float* __restrict__ o)
{
    int l = blockIdx.y;
    int i = blockIdx.x * 256 + threadIdx.x;   // 0..2*kD2-1
    float v = (i < kD2) ? a[l * kD2 + i] : b[l * kD2 + i - kD2];
    o[(size_t)l * kPU + i] = v;
}

// ---------------- embed + positional encoding ----------------
__global__ void embed_pe_kernel(const int* __restrict__ ids,
                                const float* __restrict__ embed,
                                float* __restrict__ x)
{
    int row = blockIdx.x;
    int l   = row % kL;
    int id  = ids[row];
    int d0  = threadIdx.x * 4;
    float4 ev = *(const float4*)&embed[(size_t)id * kD + d0];
    float out[4] = {ev.x, ev.y, ev.z, ev.w};
    const float negc = -0.0089944731f;   // -log(10000)/1024 in fp32
#pragma unroll
    for (int t = 0; t < 4; ++t) {
        int d  = d0 + t;
        int i2 = (d >> 1) * 2;
        float freq = expf((float)i2 * negc);
        float a    = (float)l * freq;
        out[t] += (d & 1) ? cosf(a) : sinf(a);
    }
    *(float4*)&x[(size_t)row * kD + d0] = make_float4(out[0], out[1], out[2], out[3]);
}

// ---------------- rmsnorm (emits fp16) ----------------
__global__ void rmsnorm_kernel(const float* __restrict__ x,
                               const float* __restrict__ gamma,
                               __half* __restrict__ y)
{
    int row = blockIdx.x;
    const float* xr = x + (size_t)row * kD;
    int d0 = threadIdx.x * 4;
    float4 v = *(const float4*)&xr[d0];
    float ss = v.x * v.x + v.y * v.y + v.z * v.z + v.w * v.w;
#pragma unroll
    for (int off = 16; off; off >>= 1)
        ss += __shfl_xor_sync(0xffffffffu, ss, off);
    __shared__ float ws[8];
    int lane = threadIdx.x & 31, w = threadIdx.x >> 5;
    if (lane == 0) ws[w] = ss;
    __syncthreads();
    if (w == 0) {
        float t = (lane < 8) ? ws[lane] : 0.0f;
#pragma unroll
        for (int off = 4; off; off >>= 1)
            t += __shfl_xor_sync(0xffffffffu, t, off);
        if (lane == 0) ws[0] = t;
    }
    __syncthreads();
    float scale = rsqrtf(ws[0] / (float)kD + EPSF);
    float4 g = *(const float4*)&gamma[d0];
    __half2* yp = (__half2*)&y[(size_t)row * kD + d0];
    yp[0] = __floats2half2_rn(v.x * scale * g.x, v.y * scale * g.y);
    yp[1] = __floats2half2_rn(v.z * scale * g.z, v.w * scale * g.w);
}

// ---------------- silu gate (fused proj|up input): gate = fp16(silu(proj*up)) ----------
__global__ void silu_gate_kernel(const float* __restrict__ pu,
                                 __half* __restrict__ gate)
{
    size_t t = ((size_t)blockIdx.x * blockDim.x + threadIdx.x) * 4;
    size_t row = t >> 11;        // / kD2
    int c = (int)(t & (kD2 - 1));
    const float* pr = pu + row * kPU;
    float4 p = *(const float4*)&pr[c];
    float4 u = *(const float4*)&pr[kD2 + c];
    float t0 = p.x * u.x, t1 = p.y * u.y, t2 = p.z * u.z, t3 = p.w * u.w;
    float s0 = t0 / (1.0f + __expf(-t0));
    float s1 = t1 / (1.0f + __expf(-t1));
    float s2 = t2 / (1.0f + __expf(-t2));
    float s3 = t3 / (1.0f + __expf(-t3));
    __half2* gp = (__half2*)&gate[row * kD2 + c];
    gp[0] = __floats2half2_rn(s0, s1);
    gp[1] = __floats2half2_rn(s2, s3);
}

// ================= FP16 tensor-core GEMM (R8, unchanged) =================
constexpr int kABytes = 128 * 40 * 2;      // 10240 bytes per operand tile
constexpr int kBufBytes = 2 * kABytes;     // 20480 per buffer (A+B)
constexpr int kGemmSmem = 2 * kBufBytes;   // 40960

__global__ void __launch_bounds__(256, 2)
gemm_f16_kernel(const __half* __restrict__ A, const __half* __restrict__ Bt,
                const float* __restrict__ bias, const float* __restrict__ resid,
                float* __restrict__ C, int M, int N, int K)
{
    extern __shared__ char smem[];
    uint32_t base = (uint32_t)__cvta_generic_to_shared(smem);

    int tid  = threadIdx.x;
    int lane = tid & 31;
    int warp = tid >> 5;
    int wm = warp >> 2;
    int wn = warp & 3;
    int bm = blockIdx.y, bn = blockIdx.x;

    const __half* Ab = A  + (size_t)bm * 128 * K;
    const __half* Bb = Bt + (size_t)(bn * 128) * K;

    int rw[2], sub[2];
    uint32_t dstA[2], dstB[2];
#pragma unroll
    for (int i = 0; i < 2; ++i) {
        int c = i * 256 + tid;
        rw[i]  = c >> 2;
        sub[i] = c & 3;
        dstA[i] = base + (uint32_t)(rw[i] * 80 + sub[i] * 16);
        dstB[i] = base + (uint32_t)(kABytes + rw[i] * 80 + sub[i] * 16);
    }

    int q  = lane >> 3;
    int r8 = lane & 7;
    uint32_t aAddr = base + (uint32_t)((wm * 64 + (q & 1) * 8 + r8) * 80 + (q >> 1) * 16);
    uint32_t bAddr = base + (uint32_t)(kABytes + (wn * 32 + (q & 1) * 8 + r8) * 80 + (q >> 1) * 16);

    float acc[4][4][4];
#pragma unroll
    for (int mt = 0; mt < 4; ++mt)
#pragma unroll
        for (int nt = 0; nt < 4; ++nt)
#pragma unroll
            for (int r = 0; r < 4; ++r) acc[mt][nt][r] = 0.0f;

    int nit = K >> 5;

#pragma unroll
    for (int i = 0; i < 2; ++i) {
        cp16(dstA[i], &Ab[(size_t)rw[i] * K + sub[i] * 8]);
        cp16(dstB[i], &Bb[(size_t)rw[i] * K + sub[i] * 8]);
    }
    asm volatile("cp.async.commit_group;");

    for (int it = 0; it < nit; ++it) {
        int buf = it & 1;
        uint32_t bufoff = buf ? (uint32_t)kBufBytes : 0u;
        if (it + 1 < nit) {
            int k0 = (it + 1) << 5;
            uint32_t noff = (buf ^ 1) ? (uint32_t)kBufBytes : 0u;
#pragma unroll
            for (int i = 0; i < 2; ++i) {
                cp16(dstA[i] + noff, &Ab[(size_t)rw[i] * K + k0 + sub[i] * 8]);
                cp16(dstB[i] + noff, &Bb[(size_t)rw[i] * K + k0 + sub[i] * 8]);
            }
            asm volatile("cp.async.commit_group;");
            asm volatile("cp.async.wait_group 1;");
        } else {
            asm volatile("cp.async.wait_group 0;");
        }
        __syncthreads();

#pragma unroll
        for (int ks = 0; ks < 2; ++ks) {
            uint32_t koff = bufoff + (uint32_t)(ks * 32);
            uint32_t afr[4][4], bfr[4][2];
#pragma unroll
            for (int mt = 0; mt < 4; ++mt)
                ldsm4(afr[mt][0], afr[mt][1], afr[mt][2], afr[mt][3],
                      aAddr + koff + (uint32_t)(mt * 16 * 80));
#pragma unroll
            for (int ntp = 0; ntp < 2; ++ntp) {
                uint32_t r0, r1, r2, r3;
                ldsm4(r0, r1, r2, r3, bAddr + koff + (uint32_t)(ntp * 16 * 80));
                bfr[2 * ntp][0] = r0; bfr[2 * ntp + 1][0] = r1;
                bfr[2 * ntp][1] = r2; bfr[2 * ntp + 1][1] = r3;
            }
#pragma unroll
            for (int mt = 0; mt < 4; ++mt)
#pragma unroll
                for (int nt = 0; nt < 4; ++nt)
                    mma_f16(acc[mt][nt], afr[mt], bfr[nt][0], bfr[nt][1]);
        }
        __syncthreads();
    }

    int rb = bm * 128 + wm * 64 + (lane >> 2);
    int cb = bn * 128 + wn * 32 + (lane & 3) * 2;
#pragma unroll
    for (int mt = 0; mt < 4; ++mt) {
#pragma unroll
        for (int nt = 0; nt < 4; ++nt) {
            int r0 = rb + mt * 16;
            int c0 = cb + nt * 8;
            float b0 = bias[c0], b1 = bias[c0 + 1];
            size_t off0 = (size_t)r0 * N + c0;
            size_t off1 = (size_t)(r0 + 8) * N + c0;
            float v0 = acc[mt][nt][0] + b0, v1 = acc[mt][nt][1] + b1;
            float v2 = acc[mt][nt][2] + b0, v3 = acc[mt][nt][3] + b1;
            if (resid) {
                float2 rr0 = *(const float2*)&resid[off0];
                float2 rr1 = *(const float2*)&resid[off1];
                v0 += rr0.x; v1 += rr0.y; v2 += rr1.x; v3 += rr1.y;
            }
            *(float2*)&C[off0] = make_float2(v0, v1);
            *(float2*)&C[off1] = make_float2(v2, v3);
        }
    }
}

// ================= flash attention with TF32 MMA (fused QKV input) =================
constexpr int kKV = 68;
constexpr int kAttnSmem = (64 * kKV * 2 + 4 * 16 * kKV) * 4;  // 52224 bytes

__global__ void __launch_bounds__(128)
flash_attn_mma(const float* __restrict__ QKV, __half* __restrict__ O)
{
    extern __shared__ uint32_t asmem[];
    uint32_t* Ks = asmem;
    uint32_t* Vs = asmem + 64 * kKV;
    float*    Ps = (float*)(asmem + 2 * 64 * kKV) + (threadIdx.x >> 5) * 16 * kKV;

    int tid = threadIdx.x, lane = tid & 31, w = tid >> 5;
    int g = lane >> 2, tg = lane & 3;
    int bh = blockIdx.y;
    int b  = bh >> 4;
    int h  = bh & 15;
    int q0 = blockIdx.x * 64;
    size_t baseq = ((size_t)b * kL) * kQS + (size_t)h * kDH;      // Q base (row-strided kQS)
    size_t obase = ((size_t)b * kL) * kD  + (size_t)h * kDH;      // O base
    int rlo = q0 + w * 16 + g;

    uint32_t qf[8][4];
    {
        const float* Qp = QKV + baseq + (size_t)rlo * kQS;
#pragma unroll
        for (int ks = 0; ks < 8; ++ks) {
            int kk = ks * 8 + tg;
            qf[ks][0] = f2tf32(Qp[kk]);
            qf[ks][1] = f2tf32(Qp[(size_t)8 * kQS + kk]);
            qf[ks][2] = f2tf32(Qp[kk + 4]);
            qf[ks][3] = f2tf32(Qp[(size_t)8 * kQS + kk + 4]);
        }
    }

    float of[8][4];
#pragma unroll
    for (int nt = 0; nt < 8; ++nt)
#pragma unroll
        for (int e = 0; e < 4; ++e) of[nt][e] = 0.0f;
    float mlo = -1e30f, mhi = -1e30f, llo = 0.0f, lhi = 0.0f;

    int nkt = blockIdx.x + 1;
    for (int kt = 0; kt < nkt; ++kt) {
        int k0 = kt * 64;
        __syncthreads();
#pragma unroll
        for (int i = 0; i < 8; ++i) {
            int c = i * 128 + tid;
            int row = c >> 4, f4 = (c & 15) * 4;
            size_t roff = baseq + (size_t)(k0 + row) * kQS + f4;
            float4 kv = *(const float4*)&QKV[roff + kD];        // K block
            *(uint4*)&Ks[row * kKV + f4] =
                make_uint4(f2tf32(kv.x), f2tf32(kv.y), f2tf32(kv.z), f2tf32(kv.w));
            float4 vv = *(const float4*)&QKV[roff + 2 * kD];    // V block
            *(uint4*)&Vs[row * kKV + f4] =
                make_uint4(f2tf32(vv.x), f2tf32(vv.y), f2tf32(vv.z), f2tf32(vv.w));
        }
        __syncthreads();

        float s[8][4];
#pragma unroll
        for (int nt = 0; nt < 8; ++nt)
#pragma unroll
            for (int e = 0; e < 4; ++e) s[nt][e] = 0.0f;
#pragma unroll
        for (int ks = 0; ks < 8; ++ks) {
            int kk = ks * 8 + tg;
#pragma unroll
            for (int nt = 0; nt < 8; ++nt) {
                int n0 = nt * 8 + g;
                mma_tf32(s[nt], qf[ks], Ks[n0 * kKV + kk], Ks[n0 * kKV + kk + 4]);
            }
        }

        bool diag = (kt == blockIdx.x);
        float rmlo = -1e30f, rmhi = -1e30f;
#pragma unroll
        for (int nt = 0; nt < 8; ++nt) {
#pragma unroll
            for (int e = 0; e < 4; ++e) {
                float v = s[nt][e] * 0.125f;
                if (diag) {
                    int key = k0 + nt * 8 + 2 * tg + (e & 1);
                    int row = (e < 2) ? rlo : rlo + 8;
                    if (key > row) v = -1e30f;
                }
                s[nt][e] = v;
                if (e < 2) rmlo = fmaxf(rmlo, v); else rmhi = fmaxf(rmhi, v);
            }
        }
        rmlo = fmaxf(rmlo, __shfl_xor_sync(0xffffffffu, rmlo, 1));
        rmlo = fmaxf(rmlo, __shfl_xor_sync(0xffffffffu, rmlo, 2));
        rmhi = fmaxf(rmhi, __shfl_xor_sync(0xffffffffu, rmhi, 1));
        rmhi = fmaxf(rmhi, __shfl_xor_sync(0xffffffffu, rmhi, 2));
        float mnlo = fmaxf(mlo, rmlo), mnhi = fmaxf(mhi, rmhi);
        float clo = __expf(mlo - mnlo), chi = __expf(mhi - mnhi);
        mlo = mnlo; mhi = mnhi;

        float rslo = 0.0f, rshi = 0.0f;
#pragma unroll
        for (int nt = 0; nt < 8; ++nt) {
            float p0 = __expf(s[nt][0] - mlo);
            float p1 = __expf(s[nt][1] - mlo);
            float p2 = __expf(s[nt][2] - mhi);
            float p3 = __expf(s[nt][3] - mhi);
            rslo += p0 + p1; rshi += p2 + p3;
            int col = nt * 8 + 2 * tg;
            *(float2*)&Ps[g * kKV + col]       = make_float2(p0, p1);
            *(float2*)&Ps[(g + 8) * kKV + col] = make_float2(p2, p3);
        }
        rslo += __shfl_xor_sync(0xffffffffu, rslo, 1);
        rslo += __shfl_xor_sync(0xffffffffu, rslo, 2);
        rshi += __shfl_xor_sync(0xffffffffu, rshi, 1);
        rshi += __shfl_xor_sync(0xffffffffu, rshi, 2);
        llo = llo * clo + rslo;
        lhi = lhi * chi + rshi;
#pragma unroll
        for (int nt = 0; nt < 8; ++nt) {
            of[nt][0] *= clo; of[nt][1] *= clo;
            of[nt][2] *= chi; of[nt][3] *= chi;
        }
        __syncwarp();

#pragma unroll
        for (int ks = 0; ks < 8; ++ks) {
            int kk = ks * 8 + tg;
            uint32_t pa[4];
            pa[0] = f2tf32(Ps[g * kKV + kk]);
            pa[1] = f2tf32(Ps[(g + 8) * kKV + kk]);
            pa[2] = f2tf32(Ps[g * kKV + kk + 4]);
            pa[3] = f2tf32(Ps[(g + 8) * kKV + kk + 4]);
#pragma unroll
            for (int nt = 0; nt < 8; ++nt) {
                int n0 = nt * 8 + g;
                mma_tf32(of[nt], pa, Vs[kk * kKV + n0], Vs[(kk + 4) * kKV + n0]);
            }
        }
    }

    float ilo = 1.0f / llo, ihi = 1.0f / lhi;
#pragma unroll
    for (int nt = 0; nt < 8; ++nt) {
        int col = nt * 8 + 2 * tg;
        size_t off0 = obase + (size_t)rlo * kD + col;
        size_t off1 = obase + (size_t)(rlo + 8) * kD + col;
        *(__half2*)&O[off0] = __floats2half2_rn(of[nt][0] * ilo, of[nt][1] * ilo);
        *(__half2*)&O[off1] = __floats2half2_rn(of[nt][2] * ihi, of[nt][3] * ihi);
    }
}

// ---------------- host launcher ----------------
static void launch_gemm(const __half* A, const __half* Bt, const float* bias,
                        const float* resid, float* C, int M, int N, int K)
{
    dim3 grid(N / 128, M / 128);
    gemm_f16_kernel<<<grid, 256, kGemmSmem>>>(A, Bt, bias, resid, C, M, N, K);
}
static void launch_cvt_t(const float* in, __half* out, int K, int N)
{
    dim3 grid(N / 32, K / 64);
    cvt_t_kernel<<<grid, 256>>>(in, out, K, N);
}

extern "C" void kernel_launch(void* const* d_in, const int* in_sizes, int n_in,
                              void* d_out, int out_size)
{
    const int*   ids    = (const int*)  d_in[0];
    const float* embed  = (const float*)d_in[1];
    const float* Wq     = (const float*)d_in[2];
    const float* bq     = (const float*)d_in[3];
    const float* Wk     = (const float*)d_in[4];
    const float* bk     = (const float*)d_in[5];
    const float* Wv     = (const float*)d_in[6];
    const float* bv     = (const float*)d_in[7];
    const float* Wo     = (const float*)d_in[8];
    const float* bo     = (const float*)d_in[9];
    const float* Wproj  = (const float*)d_in[10];
    const float* bproj  = (const float*)d_in[11];
    const float* Wup    = (const float*)d_in[12];
    const float* bup    = (const float*)d_in[13];
    const float* Wdown  = (const float*)d_in[14];
    const float* bdown  = (const float*)d_in[15];
    const float* gammas = (const float*)d_in[16];
    const float* Wlog   = (const float*)d_in[17];
    const float* blog   = (const float*)d_in[18];
    float* out = (float*)d_out;

    float *x, *qkv, *pu, *bqkv, *bpu;
    __half *h, *att, *gate, *wh;
    cudaGetSymbolAddress((void**)&x,    g_x);
    cudaGetSymbolAddress((void**)&qkv,  g_qkv);
    cudaGetSymbolAddress((void**)&pu,   g_pu);
    cudaGetSymbolAddress((void**)&bqkv, g_bqkv);
    cudaGetSymbolAddress((void**)&bpu,  g_bpu);
    cudaGetSymbolAddress((void**)&h,    g_h);
    cudaGetSymbolAddress((void**)&att,  g_att);
    cudaGetSymbolAddress((void**)&gate, g_gate);
    cudaGetSymbolAddress((void**)&wh,   g_wh);

    cudaFuncSetAttribute(flash_attn_mma,
                         cudaFuncAttributeMaxDynamicSharedMemorySize, kAttnSmem);

    // weight convert + transpose into fused [N][K] layouts
    for (int i = 0; i < kNL; ++i) {
        launch_cvt_t(Wq    + (size_t)i * kDD,     wh + qkvOff(i),             kD,  kD);
        launch_cvt_t(Wk    + (size_t)i * kDD,     wh + qkvOff(i) + kDD,       kD,  kD);
        launch_cvt_t(Wv    + (size_t)i * kDD,     wh + qkvOff(i) + 2 * kDD,   kD,  kD);
        launch_cvt_t(Wo    + (size_t)i * kDD,     wh + woOff(i),              kD,  kD);
        launch_cvt_t(Wproj + (size_t)i * 2 * kDD, wh + puOff(i),              kD,  kD2);
        launch_cvt_t(Wup   + (size_t)i * 2 * kDD, wh + puOff(i) + 2 * kDD,    kD,  kD2);
        launch_cvt_t(Wdown + (size_t)i * 2 * kDD, wh + dnOff(i),              kD2, kD);
    }
    launch_cvt_t(Wlog, wh + kLgBase, kD, kV);

    // fused bias vectors
    catbias3_kernel<<<dim3(kQS / 256, kNL), 256>>>(bq, bk, bv, bqkv);
    catbias2_kernel<<<dim3(kPU / 256, kNL), 256>>>(bproj, bup, bpu);

    embed_pe_kernel<<<kBL, 256>>>(ids, embed, x);

    for (int i = 0; i < kNL; ++i) {
        rmsnorm_kernel<<<kBL, 256>>>(x, gammas + (size_t)(2 * i) * kD, h);
        launch_gemm(h, wh + qkvOff(i), bqkv + (size_t)i * kQS, nullptr, qkv, kBL, kQS, kD);
        flash_attn_mma<<<dim3(kL / 64, kB * kH), 128, kAttnSmem>>>(qkv, att);
        launch_gemm(att, wh + woOff(i), bo + (size_t)i * kD, x, x, kBL, kD, kD);
        rmsnorm_kernel<<<kBL, 256>>>(x, gammas + (size_t)(2 * i + 1) * kD, h);
        launch_gemm(h, wh + puOff(i), bpu + (size_t)i * kPU, nullptr, pu, kBL, kPU, kD);
        silu_gate_kernel<<<((size_t)kBL * kD2) / (256 * 4), 256>>>(pu, gate);
        launch_gemm(gate, wh + dnOff(i), bdown + (size_t)i * kD, x, x, kBL, kD, kD2);
    }
    // convert x once for the logits GEMM A operand
    int n4 = (kBL * kD) / 4;
    cvt_h_kernel<<<(n4 + 255) / 256, 256>>>(x, h, n4);
    launch_gemm(h, wh + kLgBase, blog, nullptr, out, kBL, kV, kD);
}

// round 10
// speedup vs baseline: 2.4365x; 1.0285x over previous
#include <cuda_runtime.h>
#include <cuda_fp16.h>
#include <math.h>
#include <stdint.h>

// ---------------- problem constants ----------------
constexpr int kNL = 4;
constexpr int kD  = 1024;
constexpr int kD2 = 2048;
constexpr int kH  = 16;
constexpr int kDH = 64;
constexpr int kV  = 32000;
constexpr int kB  = 2;
constexpr int kL  = 2048;
constexpr int kBL = kB * kL;   // 4096
constexpr int kQS = 3 * kD;    // fused qkv row stride (3072)
constexpr int kPU = 2 * kD2;   // fused proj/up row stride (4096)
#define EPSF 1e-6f

// ---------------- scratch (device globals; no allocation allowed) ----------------
__device__ __align__(1024) float g_x[kBL * kD];                 // residual (fp32)
__device__ __align__(1024) float g_qkv[(size_t)kBL * kQS];      // fused q|k|v (fp32)
__device__ __align__(1024) float g_pu[(size_t)kBL * kPU];       // fused proj|up (fp32)
__device__ __align__(1024) __half g_h[kBL * kD];                // rmsnorm out / logits A
__device__ __align__(1024) __half g_att[kBL * kD];              // attention out
__device__ __align__(1024) __half g_gate[(size_t)kBL * kD2];    // silu out
__device__ __align__(1024) float g_bqkv[kNL * kQS];             // fused qkv bias
__device__ __align__(1024) float g_bpu[kNL * kPU];              // fused proj/up bias

// fp16 + TRANSPOSED weights, [N][K] blocks. Per-layer fused layouts.
constexpr size_t kDD = (size_t)kD * kD;                 // 1M
__device__ __forceinline__ __host__ size_t qkvOff(int i) { return (size_t)i * 3 * kDD; }
constexpr size_t kWoBase = (size_t)kNL * 3 * kDD;       // 12M
__device__ __forceinline__ __host__ size_t woOff(int i)  { return kWoBase + (size_t)i * kDD; }
constexpr size_t kPuBase = kWoBase + (size_t)kNL * kDD; // 16M
__device__ __forceinline__ __host__ size_t puOff(int i)  { return kPuBase + (size_t)i * 4 * kDD; }
constexpr size_t kDnBase = kPuBase + (size_t)kNL * 4 * kDD; // 32M
__device__ __forceinline__ __host__ size_t dnOff(int i)  { return kDnBase + (size_t)i * 2 * kDD; }
constexpr size_t kLgBase = kDnBase + (size_t)kNL * 2 * kDD; // 40M
constexpr size_t kWTot = kLgBase + (size_t)kD * kV;         // 72.768M
__device__ __align__(1024) __half g_wh[kWTot];

// ---------------- small helpers ----------------
__device__ __forceinline__ uint32_t f2tf32(float f) {
    uint32_t u;
    asm("cvt.rna.tf32.f32 %0, %1;" : "=r"(u) : "f"(f));
    return u;
}
__device__ __forceinline__ void mma_tf32(float* c, const uint32_t* a, uint32_t b0, uint32_t b1) {
    asm volatile(
        "mma.sync.aligned.m16n8k8.row.col.f32.tf32.tf32.f32 "
        "{%0,%1,%2,%3}, {%4,%5,%6,%7}, {%8,%9}, {%0,%1,%2,%3};"
        : "+f"(c[0]), "+f"(c[1]), "+f"(c[2]), "+f"(c[3])
        : "r"(a[0]), "r"(a[1]), "r"(a[2]), "r"(a[3]), "r"(b0), "r"(b1));
}
__device__ __forceinline__ void mma_f16(float* c, const uint32_t* a, uint32_t b0, uint32_t b1) {
    asm volatile(
        "mma.sync.aligned.m16n8k16.row.col.f32.f16.f16.f32 "
        "{%0,%1,%2,%3}, {%4,%5,%6,%7}, {%8,%9}, {%0,%1,%2,%3};"
        : "+f"(c[0]), "+f"(c[1]), "+f"(c[2]), "+f"(c[3])
        : "r"(a[0]), "r"(a[1]), "r"(a[2]), "r"(a[3]), "r"(b0), "r"(b1));
}
__device__ __forceinline__ void cp16(uint32_t dst, const void* src) {
    asm volatile("cp.async.cg.shared.global [%0], [%1], 16;" :: "r"(dst), "l"(src));
}
__device__ __forceinline__ void ldsm4(uint32_t& r0, uint32_t& r1, uint32_t& r2, uint32_t& r3,
                                      uint32_t addr) {
    asm volatile("ldmatrix.sync.aligned.m8n8.x4.shared.b16 {%0,%1,%2,%3}, [%4];"
                 : "=r"(r0), "=r"(r1), "=r"(r2), "=r"(r3) : "r"(addr));
}

// ---------------- fp16 convert + transpose (batched over layers via grid.z) ----------
// in[layer][K][N] fp32 -> out[layer][N][K] fp16. 64(K) x 32(N) tiles.
__global__ void cvt_t_kernel(const float* __restrict__ in, __half* __restrict__ out,
                             int K, int N, size_t srcStride, size_t dstStride)
{
    __shared__ __half tile[64][33];
    in  += (size_t)blockIdx.z * srcStride;
    out += (size_t)blockIdx.z * dstStride;
    int kb = blockIdx.y * 64, nb = blockIdx.x * 32;
    int tx = threadIdx.x & 31, ty = threadIdx.x >> 5;
#pragma unroll
    for (int r = ty; r < 64; r += 8)
        tile[r][tx] = __float2half_rn(in[(size_t)(kb + r) * N + nb + tx]);
    __syncthreads();
    int n  = threadIdx.x >> 3;          // 0..31
    int k0 = (threadIdx.x & 7) * 8;     // 0..56, halves
    __half2 hv[4];
#pragma unroll
    for (int j = 0; j < 4; ++j)
        hv[j] = __halves2half2(tile[k0 + 2 * j][n], tile[k0 + 2 * j + 1][n]);
    *(uint4*)&out[(size_t)(nb + n) * K + kb + k0] = *(uint4*)hv;
}

// ---------------- fp32 -> fp16 convert (logits activations) ----------------
__global__ void cvt_h_kernel(const float* __restrict__ in,
                             __half* __restrict__ out, int n4)
{
    int i = blockIdx.x * blockDim.x + threadIdx.x;
    if (i >= n4) return;
    float4 v = ((const float4*)in)[i];
    __half2* op = (__half2*)(out + (size_t)i * 4);
    op[0] = __floats2half2_rn(v.x, v.y);
    op[1] = __floats2half2_rn(v.z, v.w);
}

// ---------------- bias concat kernels ----------------
__global__ void catbias3_kernel(const float* __restrict__ a, const float* __restrict__ b,
                                const float* __restrict__ c, float* __restrict__ o)
{
    int l = blockIdx.y;
    int i = blockIdx.x * 256 + threadIdx.x;
    float v;
    if (i < kD)           v = a[l * kD + i];
    else if (i < 2 * kD)  v = b[l * kD + i - kD];
    else                  v = c[l * kD + i - 2 * kD];
    o[(size_t)l * kQS + i] = v;
}
__global__ void catbias2_kernel(const float* __restrict__ a, const float* __restrict__ b,
                                float* __restrict__ o)
{
    int l = blockIdx.y;
    int i = blockIdx.x * 256 + threadIdx.x;
    float v = (i < kD2) ? a[l * kD2 + i] : b[l * kD2 + i - kD2];
    o[(size_t)l * kPU + i] = v;
}

// ---------------- embed + positional encoding ----------------
__global__ void embed_pe_kernel(const int* __restrict__ ids,
                                const float* __restrict__ embed,
                                float* __restrict__ x)
{
    int row = blockIdx.x;
    int l   = row % kL;
    int id  = ids[row];
    int d0  = threadIdx.x * 4;
    float4 ev = *(const float4*)&embed[(size_t)id * kD + d0];
    float out[4] = {ev.x, ev.y, ev.z, ev.w};
    const float negc = -0.0089944731f;   // -log(10000)/1024 in fp32
#pragma unroll
    for (int t = 0; t < 4; ++t) {
        int d  = d0 + t;
        int i2 = (d >> 1) * 2;
        float freq = expf((float)i2 * negc);
        float a    = (float)l * freq;
        out[t] += (d & 1) ? cosf(a) : sinf(a);
    }
    *(float4*)&x[(size_t)row * kD + d0] = make_float4(out[0], out[1], out[2], out[3]);
}

// ---------------- rmsnorm (emits fp16) ----------------
__global__ void rmsnorm_kernel(const float* __restrict__ x,
                               const float* __restrict__ gamma,
                               __half* __restrict__ y)
{
    int row = blockIdx.x;
    const float* xr = x + (size_t)row * kD;
    int d0 = threadIdx.x * 4;
    float4 v = *(const float4*)&xr[d0];
    float ss = v.x * v.x + v.y * v.y + v.z * v.z + v.w * v.w;
#pragma unroll
    for (int off = 16; off; off >>= 1)
        ss += __shfl_xor_sync(0xffffffffu, ss, off);
    __shared__ float ws[8];
    int lane = threadIdx.x & 31, w = threadIdx.x >> 5;
    if (lane == 0) ws[w] = ss;
    __syncthreads();
    if (w == 0) {
        float t = (lane < 8) ? ws[lane] : 0.0f;
#pragma unroll
        for (int off = 4; off; off >>= 1)
            t += __shfl_xor_sync(0xffffffffu, t, off);
        if (lane == 0) ws[0] = t;
    }
    __syncthreads();
    float scale = rsqrtf(ws[0] / (float)kD + EPSF);
    float4 g = *(const float4*)&gamma[d0];
    __half2* yp = (__half2*)&y[(size_t)row * kD + d0];
    yp[0] = __floats2half2_rn(v.x * scale * g.x, v.y * scale * g.y);
    yp[1] = __floats2half2_rn(v.z * scale * g.z, v.w * scale * g.w);
}

// ---------------- silu gate (fused proj|up input) ----------------
__global__ void silu_gate_kernel(const float* __restrict__ pu,
                                 __half* __restrict__ gate)
{
    size_t t = ((size_t)blockIdx.x * blockDim.x + threadIdx.x) * 4;
    size_t row = t >> 11;
    int c = (int)(t & (kD2 - 1));
    const float* pr = pu + row * kPU;
    float4 p = *(const float4*)&pr[c];
    float4 u = *(const float4*)&pr[kD2 + c];
    float t0 = p.x * u.x, t1 = p.y * u.y, t2 = p.z * u.z, t3 = p.w * u.w;
    float s0 = t0 / (1.0f + __expf(-t0));
    float s1 = t1 / (1.0f + __expf(-t1));
    float s2 = t2 / (1.0f + __expf(-t2));
    float s3 = t3 / (1.0f + __expf(-t3));
    __half2* gp = (__half2*)&gate[row * kD2 + c];
    gp[0] = __floats2half2_rn(s0, s1);
    gp[1] = __floats2half2_rn(s2, s3);
}

// ================= FP16 tensor-core GEMM, 3-stage pipeline =================
// C[M,N] = A[M,K] @ Bt[N,K]^T + bias (+resid). 128x128x32 tile, 8 warps,
// m16n8k16.f16.f32, 3-stage cp.async ring, ONE __syncthreads per K-chunk.

constexpr int kABytes = 128 * 40 * 2;      // 10240 bytes per operand tile
constexpr int kBufBytes = 2 * kABytes;     // 20480 per stage (A+B)
constexpr int kGemmSmem = 3 * kBufBytes;   // 61440

__global__ void __launch_bounds__(256, 2)
gemm_f16_kernel(const __half* __restrict__ A, const __half* __restrict__ Bt,
                const float* __restrict__ bias, const float* __restrict__ resid,
                float* __restrict__ C, int M, int N, int K)
{
    extern __shared__ char smem[];
    uint32_t base = (uint32_t)__cvta_generic_to_shared(smem);

    int tid  = threadIdx.x;
    int lane = tid & 31;
    int warp = tid >> 5;
    int wm = warp >> 2;
    int wn = warp & 3;
    int bm = blockIdx.y, bn = blockIdx.x;

    const __half* Ab = A  + (size_t)bm * 128 * K;
    const __half* Bb = Bt + (size_t)(bn * 128) * K;

    int rw[2], sub[2];
    uint32_t dstA[2], dstB[2];
#pragma unroll
    for (int i = 0; i < 2; ++i) {
        int c = i * 256 + tid;
        rw[i]  = c >> 2;
        sub[i] = c & 3;
        dstA[i] = base + (uint32_t)(rw[i] * 80 + sub[i] * 16);
        dstB[i] = base + (uint32_t)(kABytes + rw[i] * 80 + sub[i] * 16);
    }

    int q  = lane >> 3;
    int r8 = lane & 7;
    uint32_t aAddr = base + (uint32_t)((wm * 64 + (q & 1) * 8 + r8) * 80 + (q >> 1) * 16);
    uint32_t bAddr = base + (uint32_t)(kABytes + (wn * 32 + (q & 1) * 8 + r8) * 80 + (q >> 1) * 16);

    float acc[4][4][4];
#pragma unroll
    for (int mt = 0; mt < 4; ++mt)
#pragma unroll
        for (int nt = 0; nt < 4; ++nt)
#pragma unroll
            for (int r = 0; r < 4; ++r) acc[mt][nt][r] = 0.0f;

    int nit = K >> 5;

    auto stage = [&](int k0, int b) {
        uint32_t boff = (uint32_t)(b * kBufBytes);
#pragma unroll
        for (int i = 0; i < 2; ++i) {
            cp16(dstA[i] + boff, &Ab[(size_t)rw[i] * K + k0 + sub[i] * 8]);
            cp16(dstB[i] + boff, &Bb[(size_t)rw[i] * K + k0 + sub[i] * 8]);
        }
        asm volatile("cp.async.commit_group;");
    };

    stage(0, 0);
    if (nit > 1) stage(32, 1);

    int buf = 0;
    for (int it = 0; it < nit; ++it) {
        if (it + 1 < nit) asm volatile("cp.async.wait_group 1;");
        else              asm volatile("cp.async.wait_group 0;");
        __syncthreads();
        if (it + 2 < nit) {
            int nb = buf + 2; if (nb >= 3) nb -= 3;
            stage((it + 2) << 5, nb);
        }
        uint32_t bufoff = (uint32_t)(buf * kBufBytes);
#pragma unroll
        for (int ks = 0; ks < 2; ++ks) {
            uint32_t koff = bufoff + (uint32_t)(ks * 32);
            uint32_t afr[4][4], bfr[4][2];
#pragma unroll
            for (int mt = 0; mt < 4; ++mt)
                ldsm4(afr[mt][0], afr[mt][1], afr[mt][2], afr[mt][3],
                      aAddr + koff + (uint32_t)(mt * 16 * 80));
#pragma unroll
            for (int ntp = 0; ntp < 2; ++ntp) {
                uint32_t r0, r1, r2, r3;
                ldsm4(r0, r1, r2, r3, bAddr + koff + (uint32_t)(ntp * 16 * 80));
                bfr[2 * ntp][0] = r0; bfr[2 * ntp + 1][0] = r1;
                bfr[2 * ntp][1] = r2; bfr[2 * ntp + 1][1] = r3;
            }
#pragma unroll
            for (int mt = 0; mt < 4; ++mt)
#pragma unroll
                for (int nt = 0; nt < 4; ++nt)
                    mma_f16(acc[mt][nt], afr[mt], bfr[nt][0], bfr[nt][1]);
        }
        if (++buf == 3) buf = 0;
    }

    int rb = bm * 128 + wm * 64 + (lane >> 2);
    int cb = bn * 128 + wn * 32 + (lane & 3) * 2;
#pragma unroll
    for (int mt = 0; mt < 4; ++mt) {
#pragma unroll
        for (int nt = 0; nt < 4; ++nt) {
            int r0 = rb + mt * 16;
            int c0 = cb + nt * 8;
            float b0 = bias[c0], b1 = bias[c0 + 1];
            size_t off0 = (size_t)r0 * N + c0;
            size_t off1 = (size_t)(r0 + 8) * N + c0;
            float v0 = acc[mt][nt][0] + b0, v1 = acc[mt][nt][1] + b1;
            float v2 = acc[mt][nt][2] + b0, v3 = acc[mt][nt][3] + b1;
            if (resid) {
                float2 rr0 = *(const float2*)&resid[off0];
                float2 rr1 = *(const float2*)&resid[off1];
                v0 += rr0.x; v1 += rr0.y; v2 += rr1.x; v3 += rr1.y;
            }
            *(float2*)&C[off0] = make_float2(v0, v1);
            *(float2*)&C[off1] = make_float2(v2, v3);
        }
    }
}

// ================= flash attention with TF32 MMA (fused QKV input) =================
constexpr int kKV = 68;
constexpr int kAttnSmem = (64 * kKV * 2 + 4 * 16 * kKV) * 4;  // 52224 bytes

__global__ void __launch_bounds__(128)
flash_attn_mma(const float* __restrict__ QKV, __half* __restrict__ O)
{
    extern __shared__ uint32_t asmem[];
    uint32_t* Ks = asmem;
    uint32_t* Vs = asmem + 64 * kKV;
    float*    Ps = (float*)(asmem + 2 * 64 * kKV) + (threadIdx.x >> 5) * 16 * kKV;

    int tid = threadIdx.x, lane = tid & 31, w = tid >> 5;
    int g = lane >> 2, tg = lane & 3;
    int bh = blockIdx.y;
    int b  = bh >> 4;
    int h  = bh & 15;
    int q0 = blockIdx.x * 64;
    size_t baseq = ((size_t)b * kL) * kQS + (size_t)h * kDH;
    size_t obase = ((size_t)b * kL) * kD  + (size_t)h * kDH;
    int rlo = q0 + w * 16 + g;

    uint32_t qf[8][4];
    {
        const float* Qp = QKV + baseq + (size_t)rlo * kQS;
#pragma unroll
        for (int ks = 0; ks < 8; ++ks) {
            int kk = ks * 8 + tg;
            qf[ks][0] = f2tf32(Qp[kk]);
            qf[ks][1] = f2tf32(Qp[(size_t)8 * kQS + kk]);
            qf[ks][2] = f2tf32(Qp[kk + 4]);
            qf[ks][3] = f2tf32(Qp[(size_t)8 * kQS + kk + 4]);
        }
    }

    float of[8][4];
#pragma unroll
    for (int nt = 0; nt < 8; ++nt)
#pragma unroll
        for (int e = 0; e < 4; ++e) of[nt][e] = 0.0f;
    float mlo = -1e30f, mhi = -1e30f, llo = 0.0f, lhi = 0.0f;

    int nkt = blockIdx.x + 1;
    for (int kt = 0; kt < nkt; ++kt) {
        int k0 = kt * 64;
        __syncthreads();
#pragma unroll
        for (int i = 0; i < 8; ++i) {
            int c = i * 128 + tid;
            int row = c >> 4, f4 = (c & 15) * 4;
            size_t roff = baseq + (size_t)(k0 + row) * kQS + f4;
            float4 kv = *(const float4*)&QKV[roff + kD];
            *(uint4*)&Ks[row * kKV + f4] =
                make_uint4(f2tf32(kv.x), f2tf32(kv.y), f2tf32(kv.z), f2tf32(kv.w));
            float4 vv = *(const float4*)&QKV[roff + 2 * kD];
            *(uint4*)&Vs[row * kKV + f4] =
                make_uint4(f2tf32(vv.x), f2tf32(vv.y), f2tf32(vv.z), f2tf32(vv.w));
        }
        __syncthreads();

        float s[8][4];
#pragma unroll
        for (int nt = 0; nt < 8; ++nt)
#pragma unroll
            for (int e = 0; e < 4; ++e) s[nt][e] = 0.0f;
#pragma unroll
        for (int ks = 0; ks < 8; ++ks) {
            int kk = ks * 8 + tg;
#pragma unroll
            for (int nt = 0; nt < 8; ++nt) {
                int n0 = nt * 8 + g;
                mma_tf32(s[nt], qf[ks], Ks[n0 * kKV + kk], Ks[n0 * kKV + kk + 4]);
            }
        }

        bool diag = (kt == blockIdx.x);
        float rmlo = -1e30f, rmhi = -1e30f;
#pragma unroll
        for (int nt = 0; nt < 8; ++nt) {
#pragma unroll
            for (int e = 0; e < 4; ++e) {
                float v = s[nt][e] * 0.125f;
                if (diag) {
                    int key = k0 + nt * 8 + 2 * tg + (e & 1);
                    int row = (e < 2) ? rlo : rlo + 8;
                    if (key > row) v = -1e30f;
                }
                s[nt][e] = v;
                if (e < 2) rmlo = fmaxf(rmlo, v); else rmhi = fmaxf(rmhi, v);
            }
        }
        rmlo = fmaxf(rmlo, __shfl_xor_sync(0xffffffffu, rmlo, 1));
        rmlo = fmaxf(rmlo, __shfl_xor_sync(0xffffffffu, rmlo, 2));
        rmhi = fmaxf(rmhi, __shfl_xor_sync(0xffffffffu, rmhi, 1));
        rmhi = fmaxf(rmhi, __shfl_xor_sync(0xffffffffu, rmhi, 2));
        float mnlo = fmaxf(mlo, rmlo), mnhi = fmaxf(mhi, rmhi);
        float clo = __expf(mlo - mnlo), chi = __expf(mhi - mnhi);
        mlo = mnlo; mhi = mnhi;

        float rslo = 0.0f, rshi = 0.0f;
#pragma unroll
        for (int nt = 0; nt < 8; ++nt) {
            float p0 = __expf(s[nt][0] - mlo);
            float p1 = __expf(s[nt][1] - mlo);
            float p2 = __expf(s[nt][2] - mhi);
            float p3 = __expf(s[nt][3] - mhi);
            rslo += p0 + p1; rshi += p2 + p3;
            int col = nt * 8 + 2 * tg;
            *(float2*)&Ps[g * kKV + col]       = make_float2(p0, p1);
            *(float2*)&Ps[(g + 8) * kKV + col] = make_float2(p2, p3);
        }
        rslo += __shfl_xor_sync(0xffffffffu, rslo, 1);
        rslo += __shfl_xor_sync(0xffffffffu, rslo, 2);
        rshi += __shfl_xor_sync(0xffffffffu, rshi, 1);
        rshi += __shfl_xor_sync(0xffffffffu, rshi, 2);
        llo = llo * clo + rslo;
        lhi = lhi * chi + rshi;
#pragma unroll
        for (int nt = 0; nt < 8; ++nt) {
            of[nt][0] *= clo; of[nt][1] *= clo;
            of[nt][2] *= chi; of[nt][3] *= chi;
        }
        __syncwarp();

#pragma unroll
        for (int ks = 0; ks < 8; ++ks) {
            int kk = ks * 8 + tg;
            uint32_t pa[4];
            pa[0] = f2tf32(Ps[g * kKV + kk]);
            pa[1] = f2tf32(Ps[(g + 8) * kKV + kk]);
            pa[2] = f2tf32(Ps[g * kKV + kk + 4]);
            pa[3] = f2tf32(Ps[(g + 8) * kKV + kk + 4]);
#pragma unroll
            for (int nt = 0; nt < 8; ++nt) {
                int n0 = nt * 8 + g;
                mma_tf32(of[nt], pa, Vs[kk * kKV + n0], Vs[(kk + 4) * kKV + n0]);
            }
        }
    }

    float ilo = 1.0f / llo, ihi = 1.0f / lhi;
#pragma unroll
    for (int nt = 0; nt < 8; ++nt) {
        int col = nt * 8 + 2 * tg;
        size_t off0 = obase + (size_t)rlo * kD + col;
        size_t off1 = obase + (size_t)(rlo + 8) * kD + col;
        *(__half2*)&O[off0] = __floats2half2_rn(of[nt][0] * ilo, of[nt][1] * ilo);
        *(__half2*)&O[off1] = __floats2half2_rn(of[nt][2] * ihi, of[nt][3] * ihi);
    }
}

// ---------------- host launcher ----------------
static void launch_gemm(const __half* A, const __half* Bt, const float* bias,
                        const float* resid, float* C, int M, int N, int K)
{
    dim3 grid(N / 128, M / 128);
    gemm_f16_kernel<<<grid, 256, kGemmSmem>>>(A, Bt, bias, resid, C, M, N, K);
}
static void launch_cvt_batch(const float* in, __half* out, int K, int N, int layers,
                             size_t sStride, size_t dStride)
{
    dim3 grid(N / 32, K / 64, layers);
    cvt_t_kernel<<<grid, 256>>>(in, out, K, N, sStride, dStride);
}

extern "C" void kernel_launch(void* const* d_in, const int* in_sizes, int n_in,
                              void* d_out, int out_size)
{
    const int*   ids    = (const int*)  d_in[0];
    const float* embed  = (const float*)d_in[1];
    const float* Wq     = (const float*)d_in[2];
    const float* bq     = (const float*)d_in[3];
    const float* Wk     = (const float*)d_in[4];
    const float* bk     = (const float*)d_in[5];
    const float* Wv     = (const float*)d_in[6];
    const float* bv     = (const float*)d_in[7];
    const float* Wo     = (const float*)d_in[8];
    const float* bo     = (const float*)d_in[9];
    const float* Wproj  = (const float*)d_in[10];
    const float* bproj  = (const float*)d_in[11];
    const float* Wup    = (const float*)d_in[12];
    const float* bup    = (const float*)d_in[13];
    const float* Wdown  = (const float*)d_in[14];
    const float* bdown  = (const float*)d_in[15];
    const float* gammas = (const float*)d_in[16];
    const float* Wlog   = (const float*)d_in[17];
    const float* blog   = (const float*)d_in[18];
    float* out = (float*)d_out;

    float *x, *qkv, *pu, *bqkv, *bpu;
    __half *h, *att, *gate, *wh;
    cudaGetSymbolAddress((void**)&x,    g_x);
    cudaGetSymbolAddress((void**)&qkv,  g_qkv);
    cudaGetSymbolAddress((void**)&pu,   g_pu);
    cudaGetSymbolAddress((void**)&bqkv, g_bqkv);
    cudaGetSymbolAddress((void**)&bpu,  g_bpu);
    cudaGetSymbolAddress((void**)&h,    g_h);
    cudaGetSymbolAddress((void**)&att,  g_att);
    cudaGetSymbolAddress((void**)&gate, g_gate);
    cudaGetSymbolAddress((void**)&wh,   g_wh);

    cudaFuncSetAttribute(gemm_f16_kernel,
                         cudaFuncAttributeMaxDynamicSharedMemorySize, kGemmSmem);
    cudaFuncSetAttribute(flash_attn_mma,
                         cudaFuncAttributeMaxDynamicSharedMemorySize, kAttnSmem);

    // weight convert + transpose, batched per kind across layers (8 launches)
    launch_cvt_batch(Wq,    wh + qkvOff(0),           kD,  kD,  kNL, kDD,     3 * kDD);
    launch_cvt_batch(Wk,    wh + qkvOff(0) + kDD,     kD,  kD,  kNL, kDD,     3 * kDD);
    launch_cvt_batch(Wv,    wh + qkvOff(0) + 2 * kDD, kD,  kD,  kNL, kDD,     3 * kDD);
    launch_cvt_batch(Wo,    wh + kWoBase,             kD,  kD,  kNL, kDD,     kDD);
    launch_cvt_batch(Wproj, wh + kPuBase,             kD,  kD2, kNL, 2 * kDD, 4 * kDD);
    launch_cvt_batch(Wup,   wh + kPuBase + 2 * kDD,   kD,  kD2, kNL, 2 * kDD, 4 * kDD);
    launch_cvt_batch(Wdown, wh + kDnBase,             kD2, kD,  kNL, 2 * kDD, 2 * kDD);
    launch_cvt_batch(Wlog,  wh + kLgBase,             kD,  kV,  1,   0,       0);

    catbias3_kernel<<<dim3(kQS / 256, kNL), 256>>>(bq, bk, bv, bqkv);
    catbias2_kernel<<<dim3(kPU / 256, kNL), 256>>>(bproj, bup, bpu);

    embed_pe_kernel<<<kBL, 256>>>(ids, embed, x);

    for (int i = 0; i < kNL; ++i) {
        rmsnorm_kernel<<<kBL, 256>>>(x, gammas + (size_t)(2 * i) * kD, h);
        launch_gemm(h, wh + qkvOff(i), bqkv + (size_t)i * kQS, nullptr, qkv, kBL, kQS, kD);
        flash_attn_mma<<<dim3(kL / 64, kB * kH), 128, kAttnSmem>>>(qkv, att);
        launch_gemm(att, wh + woOff(i), bo + (size_t)i * kD, x, x, kBL, kD, kD);
        rmsnorm_kernel<<<kBL, 256>>>(x, gammas + (size_t)(2 * i + 1) * kD, h);
        launch_gemm(h, wh + puOff(i), bpu + (size_t)i * kPU, nullptr, pu, kBL, kPU, kD);
        silu_gate_kernel<<<((size_t)kBL * kD2) / (256 * 4), 256>>>(pu, gate);
        launch_gemm(gate, wh + dnOff(i), bdown + (size_t)i * kD, x, x, kBL, kD, kD2);
    }
    int n4 = (kBL * kD) / 4;
    cvt_h_kernel<<<(n4 + 255) / 256, 256>>>(x, h, n4);
    launch_gemm(h, wh + kLgBase, blog, nullptr, out, kBL, kV, kD);
}